// round 4
// baseline (speedup 1.0000x reference)
#include <cuda_runtime.h>
#include <cstdint>
#include <mma.h>
#include <math.h>

using namespace nvcuda;

#define HEADS   8
#define DK      64
#define DV      64
#define NSEQ    49
#define GRID7   7
#define DMODEL  512
#define BATCH   2048
#define MROWS   (BATCH * NSEQ)   // 100352

// ---------------- scratch (no allocations allowed) ----------------
__device__ float g_q[(size_t)MROWS * DMODEL];
__device__ float g_k[(size_t)MROWS * DMODEL];
__device__ float g_v[(size_t)MROWS * DMODEL];
__device__ float g_att[(size_t)MROWS * DMODEL];

// ---------------- cp.async helpers ----------------
__device__ __forceinline__ void cp_async16(void* smem, const void* gmem) {
    uint32_t s = (uint32_t)__cvta_generic_to_shared(smem);
    asm volatile("cp.async.cg.shared.global [%0], [%1], 16;\n" :: "r"(s), "l"(gmem));
}
__device__ __forceinline__ void cp_commit() {
    asm volatile("cp.async.commit_group;\n");
}
template <int N>
__device__ __forceinline__ void cp_wait() {
    asm volatile("cp.async.wait_group %0;\n" :: "n"(N));
}

// =====================================================================
// tf32 WMMA GEMM body with 2-stage cp.async pipeline.
//   C[M,N] = A[M,K] @ W[N,K]^T + bias
// BM=128, BN in {128,64}, BK=32, 256 threads (8 warps in 4x2 grid).
// =====================================================================
template <int BM, int BN, int BK>
__device__ __forceinline__
void gemm_body(const float* __restrict__ A, const float* __restrict__ W,
               const float* __restrict__ bias, float* __restrict__ C,
               int M, int N, int K)
{
    constexpr int BKP     = BK + 4;
    constexpr int WARPS_N = 2;
    constexpr int WM      = BM / 4;         // 32
    constexpr int WN      = BN / WARPS_N;   // 64 or 32
    constexpr int MF      = WM / 16;        // 2
    constexpr int NF      = WN / 16;        // 4 or 2
    constexpr int A_V4    = BM * (BK / 4);
    constexpr int W_V4    = BN * (BK / 4);

    __shared__ float As[2][BM][BKP];
    __shared__ float Ws[2][BN][BKP];
    __shared__ float stage[8][16][20];

    const int tid  = threadIdx.x;
    const int warp = tid >> 5;
    const int lane = tid & 31;
    const int wm   = warp / WARPS_N;
    const int wn   = warp % WARPS_N;
    const int m0   = blockIdx.y * BM;
    const int n0   = blockIdx.x * BN;

    wmma::fragment<wmma::accumulator, 16, 16, 8, float> acc[MF][NF];
#pragma unroll
    for (int mf = 0; mf < MF; mf++)
#pragma unroll
        for (int nf = 0; nf < NF; nf++)
            wmma::fill_fragment(acc[mf][nf], 0.0f);

    const int nk = K / BK;

    auto issue_stage = [&](int kc, int buf) {
#pragma unroll
        for (int idx = tid; idx < A_V4; idx += 256) {
            int row = idx / (BK / 4);
            int col = (idx % (BK / 4)) * 4;
            cp_async16(&As[buf][row][col],
                       &A[(size_t)(m0 + row) * K + kc * BK + col]);
        }
#pragma unroll
        for (int idx = tid; idx < W_V4; idx += 256) {
            int row = idx / (BK / 4);
            int col = (idx % (BK / 4)) * 4;
            cp_async16(&Ws[buf][row][col],
                       &W[(size_t)(n0 + row) * K + kc * BK + col]);
        }
        cp_commit();
    };

    issue_stage(0, 0);

    for (int kc = 0; kc < nk; kc++) {
        const int buf = kc & 1;
        if (kc + 1 < nk) { issue_stage(kc + 1, buf ^ 1); cp_wait<1>(); }
        else            { cp_wait<0>(); }
        __syncthreads();

#pragma unroll
        for (int ks = 0; ks < BK; ks += 8) {
            wmma::fragment<wmma::matrix_a, 16, 16, 8,
                           wmma::precision::tf32, wmma::row_major> af[MF];
            wmma::fragment<wmma::matrix_b, 16, 16, 8,
                           wmma::precision::tf32, wmma::col_major> bf[NF];
#pragma unroll
            for (int mf = 0; mf < MF; mf++) {
                wmma::load_matrix_sync(af[mf], &As[buf][wm * WM + mf * 16][ks], BKP);
#pragma unroll
                for (int e = 0; e < af[mf].num_elements; e++)
                    af[mf].x[e] = wmma::__float_to_tf32(af[mf].x[e]);
            }
#pragma unroll
            for (int nf = 0; nf < NF; nf++) {
                wmma::load_matrix_sync(bf[nf], &Ws[buf][wn * WN + nf * 16][ks], BKP);
#pragma unroll
                for (int e = 0; e < bf[nf].num_elements; e++)
                    bf[nf].x[e] = wmma::__float_to_tf32(bf[nf].x[e]);
            }
#pragma unroll
            for (int mf = 0; mf < MF; mf++)
#pragma unroll
                for (int nf = 0; nf < NF; nf++)
                    wmma::mma_sync(acc[mf][nf], af[mf], bf[nf], acc[mf][nf]);
        }
        __syncthreads();
    }

    // ---- epilogue: stage fragment, add bias, vector store ----
#pragma unroll
    for (int mf = 0; mf < MF; mf++)
#pragma unroll
        for (int nf = 0; nf < NF; nf++) {
            wmma::store_matrix_sync(&stage[warp][0][0], acc[mf][nf], 20,
                                    wmma::mem_row_major);
            __syncwarp();
            int r  = lane >> 1;
            int c  = (lane & 1) * 8;
            int gm = m0 + wm * WM + mf * 16 + r;
            int gn = n0 + wn * WN + nf * 16 + c;
            float4 v0 = *reinterpret_cast<float4*>(&stage[warp][r][c]);
            float4 v1 = *reinterpret_cast<float4*>(&stage[warp][r][c + 4]);
            float4 b0 = *reinterpret_cast<const float4*>(&bias[gn]);
            float4 b1 = *reinterpret_cast<const float4*>(&bias[gn + 4]);
            v0.x += b0.x; v0.y += b0.y; v0.z += b0.z; v0.w += b0.w;
            v1.x += b1.x; v1.y += b1.y; v1.z += b1.z; v1.w += b1.w;
            *reinterpret_cast<float4*>(&C[(size_t)gm * N + gn])     = v0;
            *reinterpret_cast<float4*>(&C[(size_t)gm * N + gn + 4]) = v1;
            __syncwarp();
        }
}

// Fused QKV: blockIdx.z selects (input, weight, bias, output).
template <int BM, int BN, int BK>
__global__ __launch_bounds__(256)
void qkv_gemm_kernel(const float* Aq, const float* Ak, const float* Av,
                     const float* Wq, const float* Wk, const float* Wv,
                     const float* bq, const float* bk, const float* bv,
                     float* Cq, float* Ck, float* Cv, int M, int N, int K)
{
    const int z = blockIdx.z;
    const float* A = (z == 0) ? Aq : (z == 1) ? Ak : Av;
    const float* W = (z == 0) ? Wq : (z == 1) ? Wk : Wv;
    const float* b = (z == 0) ? bq : (z == 1) ? bk : bv;
    float*       C = (z == 0) ? Cq : (z == 1) ? Ck : Cv;
    gemm_body<BM, BN, BK>(A, W, b, C, M, N, K);
}

template <int BM, int BN, int BK>
__global__ __launch_bounds__(256)
void gemm_single_kernel(const float* A, const float* W, const float* b,
                        float* C, int M, int N, int K)
{
    gemm_body<BM, BN, BK>(A, W, b, C, M, N, K);
}

// =====================================================================
// Sparse dilated attention (float4-vectorized LDS).
//   w_ij = exp(s_ij) - 1 for Chebyshev-1 neighbors;
//   O_i  = (Vsum + sum w_ij v_j) / (49 + sum w_ij)
// =====================================================================
__global__ __launch_bounds__(256)
void dilate_attention_sparse(const float* __restrict__ q,
                             const float* __restrict__ k,
                             const float* __restrict__ v,
                             float* __restrict__ out)
{
    __shared__ float4 qs4[NSEQ][16];
    __shared__ float4 ks4[NSEQ][17];   // +1 float4 pad: stagger rows across banks
    __shared__ float4 vs4[NSEQ][16];
    __shared__ float4 vsum4[16];
    __shared__ float  wgt[NSEQ][8];
    __shared__ float  zinv[NSEQ];
    __shared__ int    nbr[NSEQ][8];
    __shared__ int    cnt[NSEQ];

    const int h   = blockIdx.x;
    const int b   = blockIdx.y;
    const int tid = threadIdx.x;
    const size_t base = (size_t)b * NSEQ * DMODEL + (size_t)h * DK;

    // ---- load q,k,v tiles as float4 (coalesced) ----
    for (int e = tid; e < NSEQ * 16; e += 256) {
        int n = e >> 4, d4 = e & 15;
        size_t g = (base + (size_t)n * DMODEL) / 4 + d4;
        qs4[n][d4] = reinterpret_cast<const float4*>(q)[g];
        ks4[n][d4] = reinterpret_cast<const float4*>(k)[g];
        vs4[n][d4] = reinterpret_cast<const float4*>(v)[g];
    }
    // ---- neighbor lists ----
    if (tid < NSEQ) {
        int r = tid / GRID7, c = tid % GRID7;
        int n = 0;
#pragma unroll
        for (int dr = -1; dr <= 1; dr++)
#pragma unroll
            for (int dc = -1; dc <= 1; dc++) {
                if (dr == 0 && dc == 0) continue;
                int rr = r + dr, cc = c + dc;
                if (rr >= 0 && rr < GRID7 && cc >= 0 && cc < GRID7)
                    nbr[tid][n++] = rr * GRID7 + cc;
            }
        cnt[tid] = n;
        for (int l = n; l < 8; l++) nbr[tid][l] = 0;
    }
    __syncthreads();

    // ---- Vsum (threads 224..239 each own one float4 column) ----
    if (tid >= 224 && tid < 240) {
        int d4 = tid - 224;
        float4 s = make_float4(0.f, 0.f, 0.f, 0.f);
#pragma unroll
        for (int j = 0; j < NSEQ; j++) {
            float4 t = vs4[j][d4];
            s.x += t.x; s.y += t.y; s.z += t.z; s.w += t.w;
        }
        vsum4[d4] = s;
    }

    // ---- sparse QK dots ----
    for (int t = tid; t < NSEQ * 8; t += 256) {
        int i = t >> 3, l = t & 7;
        float w = 0.0f;
        if (l < cnt[i]) {
            int j = nbr[i][l];
            float dot = 0.0f;
#pragma unroll
            for (int d4 = 0; d4 < 16; d4++) {
                float4 a  = qs4[i][d4];
                float4 bb = ks4[j][d4];
                dot += a.x * bb.x + a.y * bb.y + a.z * bb.z + a.w * bb.w;
            }
            w = __expf(dot * 0.125f) - 1.0f;
        }
        wgt[i][l] = w;
    }
    __syncthreads();

    // ---- normalizer ----
    if (tid < NSEQ) {
        float z = (float)NSEQ;
#pragma unroll
        for (int l = 0; l < 8; l++) z += wgt[tid][l];
        zinv[tid] = 1.0f / z;
    }
    __syncthreads();

    // ---- output (one float4 per thread-slot) ----
    for (int t = tid; t < NSEQ * 16; t += 256) {
        int i = t >> 4, d4 = t & 15;
        float4 acc = vsum4[d4];
#pragma unroll
        for (int l = 0; l < 8; l++) {
            float w = wgt[i][l];
            float4 vv = vs4[nbr[i][l]][d4];
            acc.x += w * vv.x; acc.y += w * vv.y;
            acc.z += w * vv.z; acc.w += w * vv.w;
        }
        float zi = zinv[i];
        acc.x *= zi; acc.y *= zi; acc.z *= zi; acc.w *= zi;
        reinterpret_cast<float4*>(out)[(base + (size_t)i * DMODEL) / 4 + d4] = acc;
    }
}

// ---------------- launch ----------------
extern "C" void kernel_launch(void* const* d_in, const int* in_sizes, int n_in,
                              void* d_out, int out_size)
{
    const float* queries = (const float*)d_in[0];
    const float* keys    = (const float*)d_in[1];
    const float* values  = (const float*)d_in[2];
    const float* Wq      = (const float*)d_in[3];
    const float* bq      = (const float*)d_in[4];
    const float* Wk      = (const float*)d_in[5];
    const float* bk      = (const float*)d_in[6];
    const float* Wv      = (const float*)d_in[7];
    const float* bv      = (const float*)d_in[8];
    const float* Wo      = (const float*)d_in[9];
    const float* bo      = (const float*)d_in[10];

    float *q, *k, *v, *att;
    cudaGetSymbolAddress((void**)&q,   g_q);
    cudaGetSymbolAddress((void**)&k,   g_k);
    cudaGetSymbolAddress((void**)&v,   g_v);
    cudaGetSymbolAddress((void**)&att, g_att);

    // fused QKV projections: M=100352, N=512, K=512 (tf32 + cp.async pipeline)
    dim3 gridQKV(DMODEL / 128, MROWS / 128, 3);
    qkv_gemm_kernel<128, 128, 32><<<gridQKV, 256>>>(
        queries, keys, values, Wq, Wk, Wv, bq, bk, bv,
        q, k, v, MROWS, DMODEL, DMODEL);

    // sparse dilated attention: one block per (b, h)
    dilate_attention_sparse<<<dim3(HEADS, BATCH), 256>>>(q, k, v, att);

    // output projection: M=100352, N=64, K=512
    dim3 gridO(1, MROWS / 128);
    gemm_single_kernel<128, 64, 32><<<gridO, 256>>>(
        att, Wo, bo, (float*)d_out, MROWS, 64, DMODEL);
}

// round 5
// speedup vs baseline: 1.5746x; 1.5746x over previous
#include <cuda_runtime.h>
#include <cstdint>
#include <mma.h>
#include <math.h>

using namespace nvcuda;

#define HEADS   8
#define DK      64
#define DV      64
#define NSEQ    49
#define GRID7   7
#define DMODEL  512
#define BATCH   2048
#define MROWS   (BATCH * NSEQ)   // 100352

// ---------------- scratch (no allocations allowed) ----------------
__device__ float g_q[(size_t)MROWS * DMODEL];
__device__ float g_k[(size_t)MROWS * DMODEL];
__device__ float g_v[(size_t)MROWS * DMODEL];
__device__ float g_att[(size_t)MROWS * DMODEL];

// ---------------- cp.async helpers ----------------
__device__ __forceinline__ void cp_async16(void* smem, const void* gmem) {
    uint32_t s = (uint32_t)__cvta_generic_to_shared(smem);
    asm volatile("cp.async.cg.shared.global [%0], [%1], 16;\n" :: "r"(s), "l"(gmem));
}
__device__ __forceinline__ void cp_commit() {
    asm volatile("cp.async.commit_group;\n");
}
template <int N>
__device__ __forceinline__ void cp_wait() {
    asm volatile("cp.async.wait_group %0;\n" :: "n"(N));
}

// =====================================================================
// tf32 WMMA GEMM body, 2-stage cp.async pipeline, 32x32 warp tiles.
//   C[M,N] = A[M,K] @ W[N,K]^T + bias
// Warp grid WARPS_M x WARPS_N, each warp owns a 32x32 tile (MF=NF=2,
// 32 accumulator regs/thread) -> low register pressure -> more warps/SM.
// Epilogue staging buffer is aliased onto the As smem region.
// =====================================================================
template <int BM, int BN, int BK, int WARPS_M, int WARPS_N>
__device__ __forceinline__
void gemm_body(const float* __restrict__ A, const float* __restrict__ W,
               const float* __restrict__ bias, float* __restrict__ C,
               int M, int N, int K)
{
    constexpr int NTHREADS = WARPS_M * WARPS_N * 32;
    constexpr int NWARPS   = WARPS_M * WARPS_N;
    constexpr int BKP      = BK + 4;
    constexpr int WM       = BM / WARPS_M;   // 32
    constexpr int WN       = BN / WARPS_N;   // 32
    constexpr int MF       = WM / 16;        // 2
    constexpr int NF       = WN / 16;        // 2
    constexpr int A_V4     = BM * (BK / 4);
    constexpr int W_V4     = BN * (BK / 4);
    constexpr int A_BYTES  = 2 * BM * BKP * 4;
    constexpr int W_BYTES  = 2 * BN * BKP * 4;
    static_assert(NWARPS * 16 * 20 * 4 <= A_BYTES, "stage must fit in As alias");

    __shared__ __align__(16) unsigned char smem_raw[A_BYTES + W_BYTES];
    typedef float (*TileA)[BM][BKP];
    typedef float (*TileW)[BN][BKP];
    TileA As = reinterpret_cast<TileA>(smem_raw);
    TileW Ws = reinterpret_cast<TileW>(smem_raw + A_BYTES);
    float (*stage)[16][20] = reinterpret_cast<float (*)[16][20]>(smem_raw);

    const int tid  = threadIdx.x;
    const int warp = tid >> 5;
    const int lane = tid & 31;
    const int wm   = warp / WARPS_N;
    const int wn   = warp % WARPS_N;
    const int m0   = blockIdx.y * BM;
    const int n0   = blockIdx.x * BN;

    wmma::fragment<wmma::accumulator, 16, 16, 8, float> acc[MF][NF];
#pragma unroll
    for (int mf = 0; mf < MF; mf++)
#pragma unroll
        for (int nf = 0; nf < NF; nf++)
            wmma::fill_fragment(acc[mf][nf], 0.0f);

    const int nk = K / BK;

    auto issue_stage = [&](int kc, int buf) {
#pragma unroll
        for (int idx = tid; idx < A_V4; idx += NTHREADS) {
            int row = idx / (BK / 4);
            int col = (idx % (BK / 4)) * 4;
            cp_async16(&As[buf][row][col],
                       &A[(size_t)(m0 + row) * K + kc * BK + col]);
        }
#pragma unroll
        for (int idx = tid; idx < W_V4; idx += NTHREADS) {
            int row = idx / (BK / 4);
            int col = (idx % (BK / 4)) * 4;
            cp_async16(&Ws[buf][row][col],
                       &W[(size_t)(n0 + row) * K + kc * BK + col]);
        }
        cp_commit();
    };

    issue_stage(0, 0);

    for (int kc = 0; kc < nk; kc++) {
        const int buf = kc & 1;
        if (kc + 1 < nk) { issue_stage(kc + 1, buf ^ 1); cp_wait<1>(); }
        else            { cp_wait<0>(); }
        __syncthreads();

#pragma unroll
        for (int ks = 0; ks < BK; ks += 8) {
            wmma::fragment<wmma::matrix_a, 16, 16, 8,
                           wmma::precision::tf32, wmma::row_major> af[MF];
            wmma::fragment<wmma::matrix_b, 16, 16, 8,
                           wmma::precision::tf32, wmma::col_major> bf[NF];
#pragma unroll
            for (int mf = 0; mf < MF; mf++) {
                wmma::load_matrix_sync(af[mf], &As[buf][wm * WM + mf * 16][ks], BKP);
#pragma unroll
                for (int e = 0; e < af[mf].num_elements; e++)
                    af[mf].x[e] = wmma::__float_to_tf32(af[mf].x[e]);
            }
#pragma unroll
            for (int nf = 0; nf < NF; nf++) {
                wmma::load_matrix_sync(bf[nf], &Ws[buf][wn * WN + nf * 16][ks], BKP);
#pragma unroll
                for (int e = 0; e < bf[nf].num_elements; e++)
                    bf[nf].x[e] = wmma::__float_to_tf32(bf[nf].x[e]);
            }
#pragma unroll
            for (int mf = 0; mf < MF; mf++)
#pragma unroll
                for (int nf = 0; nf < NF; nf++)
                    wmma::mma_sync(acc[mf][nf], af[mf], bf[nf], acc[mf][nf]);
        }
        __syncthreads();   // also protects the stage alias below
    }

    // ---- epilogue: stage fragment (aliased smem), add bias, vector store ----
#pragma unroll
    for (int mf = 0; mf < MF; mf++)
#pragma unroll
        for (int nf = 0; nf < NF; nf++) {
            wmma::store_matrix_sync(&stage[warp][0][0], acc[mf][nf], 20,
                                    wmma::mem_row_major);
            __syncwarp();
            int r  = lane >> 1;
            int c  = (lane & 1) * 8;
            int gm = m0 + wm * WM + mf * 16 + r;
            int gn = n0 + wn * WN + nf * 16 + c;
            float4 v0 = *reinterpret_cast<float4*>(&stage[warp][r][c]);
            float4 v1 = *reinterpret_cast<float4*>(&stage[warp][r][c + 4]);
            float4 b0 = *reinterpret_cast<const float4*>(&bias[gn]);
            float4 b1 = *reinterpret_cast<const float4*>(&bias[gn + 4]);
            v0.x += b0.x; v0.y += b0.y; v0.z += b0.z; v0.w += b0.w;
            v1.x += b1.x; v1.y += b1.y; v1.z += b1.z; v1.w += b1.w;
            *reinterpret_cast<float4*>(&C[(size_t)gm * N + gn])     = v0;
            *reinterpret_cast<float4*>(&C[(size_t)gm * N + gn + 4]) = v1;
            __syncwarp();
        }
}

// Fused QKV: blockIdx.z selects (input, weight, bias, output).
__global__ __launch_bounds__(512, 1)
void qkv_gemm_kernel(const float* Aq, const float* Ak, const float* Av,
                     const float* Wq, const float* Wk, const float* Wv,
                     const float* bq, const float* bk, const float* bv,
                     float* Cq, float* Ck, float* Cv, int M, int N, int K)
{
    const int z = blockIdx.z;
    const float* A = (z == 0) ? Aq : (z == 1) ? Ak : Av;
    const float* W = (z == 0) ? Wq : (z == 1) ? Wk : Wv;
    const float* b = (z == 0) ? bq : (z == 1) ? bk : bv;
    float*       C = (z == 0) ? Cq : (z == 1) ? Ck : Cv;
    gemm_body<128, 128, 32, 4, 4>(A, W, b, C, M, N, K);
}

__global__ __launch_bounds__(256, 2)
void out_gemm_kernel(const float* A, const float* W, const float* b,
                     float* C, int M, int N, int K)
{
    gemm_body<128, 64, 32, 4, 2>(A, W, b, C, M, N, K);
}

// =====================================================================
// Sparse dilated attention (float4-vectorized LDS).
//   w_ij = exp(s_ij) - 1 for Chebyshev-1 neighbors;
//   O_i  = (Vsum + sum w_ij v_j) / (49 + sum w_ij)
// =====================================================================
__global__ __launch_bounds__(256)
void dilate_attention_sparse(const float* __restrict__ q,
                             const float* __restrict__ k,
                             const float* __restrict__ v,
                             float* __restrict__ out)
{
    __shared__ float4 qs4[NSEQ][16];
    __shared__ float4 ks4[NSEQ][17];   // +1 float4 pad: stagger rows across banks
    __shared__ float4 vs4[NSEQ][16];
    __shared__ float4 vsum4[16];
    __shared__ float  wgt[NSEQ][8];
    __shared__ float  zinv[NSEQ];
    __shared__ int    nbr[NSEQ][8];
    __shared__ int    cnt[NSEQ];

    const int h   = blockIdx.x;
    const int b   = blockIdx.y;
    const int tid = threadIdx.x;
    const size_t base = (size_t)b * NSEQ * DMODEL + (size_t)h * DK;

    // ---- load q,k,v tiles as float4 (coalesced) ----
    for (int e = tid; e < NSEQ * 16; e += 256) {
        int n = e >> 4, d4 = e & 15;
        size_t g = (base + (size_t)n * DMODEL) / 4 + d4;
        qs4[n][d4] = reinterpret_cast<const float4*>(q)[g];
        ks4[n][d4] = reinterpret_cast<const float4*>(k)[g];
        vs4[n][d4] = reinterpret_cast<const float4*>(v)[g];
    }
    // ---- neighbor lists ----
    if (tid < NSEQ) {
        int r = tid / GRID7, c = tid % GRID7;
        int n = 0;
#pragma unroll
        for (int dr = -1; dr <= 1; dr++)
#pragma unroll
            for (int dc = -1; dc <= 1; dc++) {
                if (dr == 0 && dc == 0) continue;
                int rr = r + dr, cc = c + dc;
                if (rr >= 0 && rr < GRID7 && cc >= 0 && cc < GRID7)
                    nbr[tid][n++] = rr * GRID7 + cc;
            }
        cnt[tid] = n;
        for (int l = n; l < 8; l++) nbr[tid][l] = 0;
    }
    __syncthreads();

    // ---- Vsum (threads 224..239 each own one float4 column) ----
    if (tid >= 224 && tid < 240) {
        int d4 = tid - 224;
        float4 s = make_float4(0.f, 0.f, 0.f, 0.f);
#pragma unroll
        for (int j = 0; j < NSEQ; j++) {
            float4 t = vs4[j][d4];
            s.x += t.x; s.y += t.y; s.z += t.z; s.w += t.w;
        }
        vsum4[d4] = s;
    }

    // ---- sparse QK dots ----
    for (int t = tid; t < NSEQ * 8; t += 256) {
        int i = t >> 3, l = t & 7;
        float w = 0.0f;
        if (l < cnt[i]) {
            int j = nbr[i][l];
            float dot = 0.0f;
#pragma unroll
            for (int d4 = 0; d4 < 16; d4++) {
                float4 a  = qs4[i][d4];
                float4 bb = ks4[j][d4];
                dot += a.x * bb.x + a.y * bb.y + a.z * bb.z + a.w * bb.w;
            }
            w = __expf(dot * 0.125f) - 1.0f;
        }
        wgt[i][l] = w;
    }
    __syncthreads();

    // ---- normalizer ----
    if (tid < NSEQ) {
        float z = (float)NSEQ;
#pragma unroll
        for (int l = 0; l < 8; l++) z += wgt[tid][l];
        zinv[tid] = 1.0f / z;
    }
    __syncthreads();

    // ---- output (one float4 per thread-slot) ----
    for (int t = tid; t < NSEQ * 16; t += 256) {
        int i = t >> 4, d4 = t & 15;
        float4 acc = vsum4[d4];
#pragma unroll
        for (int l = 0; l < 8; l++) {
            float w = wgt[i][l];
            float4 vv = vs4[nbr[i][l]][d4];
            acc.x += w * vv.x; acc.y += w * vv.y;
            acc.z += w * vv.z; acc.w += w * vv.w;
        }
        float zi = zinv[i];
        acc.x *= zi; acc.y *= zi; acc.z *= zi; acc.w *= zi;
        reinterpret_cast<float4*>(out)[(base + (size_t)i * DMODEL) / 4 + d4] = acc;
    }
}

// ---------------- launch ----------------
extern "C" void kernel_launch(void* const* d_in, const int* in_sizes, int n_in,
                              void* d_out, int out_size)
{
    const float* queries = (const float*)d_in[0];
    const float* keys    = (const float*)d_in[1];
    const float* values  = (const float*)d_in[2];
    const float* Wq      = (const float*)d_in[3];
    const float* bq      = (const float*)d_in[4];
    const float* Wk      = (const float*)d_in[5];
    const float* bk      = (const float*)d_in[6];
    const float* Wv      = (const float*)d_in[7];
    const float* bv      = (const float*)d_in[8];
    const float* Wo      = (const float*)d_in[9];
    const float* bo      = (const float*)d_in[10];

    float *q, *k, *v, *att;
    cudaGetSymbolAddress((void**)&q,   g_q);
    cudaGetSymbolAddress((void**)&k,   g_k);
    cudaGetSymbolAddress((void**)&v,   g_v);
    cudaGetSymbolAddress((void**)&att, g_att);

    // fused QKV projections: M=100352, N=512, K=512 (tf32 + cp.async pipeline)
    dim3 gridQKV(DMODEL / 128, MROWS / 128, 3);
    qkv_gemm_kernel<<<gridQKV, 512>>>(
        queries, keys, values, Wq, Wk, Wv, bq, bk, bv,
        q, k, v, MROWS, DMODEL, DMODEL);

    // sparse dilated attention: one block per (b, h)
    dilate_attention_sparse<<<dim3(HEADS, BATCH), 256>>>(q, k, v, att);

    // output projection: M=100352, N=64, K=512
    dim3 gridO(1, MROWS / 128);
    out_gemm_kernel<<<gridO, 256>>>(
        att, Wo, bo, (float*)d_out, MROWS, 64, DMODEL);
}

// round 8
// speedup vs baseline: 2.9551x; 1.8768x over previous
#include <cuda_runtime.h>
#include <cuda_fp16.h>
#include <cstdint>
#include <mma.h>
#include <math.h>

using namespace nvcuda;

#define HEADS   8
#define NSEQ    49
#define GRID7   7
#define DMODEL  512
#define BATCH   2048
#define MROWS   (BATCH * NSEQ)   // 100352 = 784 * 128
#define MTILES  (MROWS / 128)    // 784

// ---------------- scratch (no allocations allowed) ----------------
__device__ float  g_q [(size_t)MROWS * DMODEL];     // q projection (fp32)
__device__ float  g_k [(size_t)MROWS * DMODEL];     // k projection (fp32)
__device__ float  g_vo[(size_t)MROWS * DMODEL];     // vo = values @ Wvo^T (fp32)
__device__ __half g_qh[(size_t)MROWS * DMODEL];     // half copies of inputs
__device__ __half g_kh[(size_t)MROWS * DMODEL];
__device__ __half g_vh[(size_t)MROWS * DMODEL];
__device__ __half g_wqh[DMODEL * DMODEL];
__device__ __half g_wkh[DMODEL * DMODEL];
__device__ __half g_wvoh[DMODEL * DMODEL];
__device__ float  g_bvo[DMODEL];

// ---------------- small helpers ----------------
__device__ __forceinline__ uint32_t h2_bits(__half2 h) {
    union { __half2 h; uint32_t u; } cvt; cvt.h = h; return cvt.u;
}
__device__ __forceinline__ uint2 pack4(float x, float y, float z, float w) {
    return make_uint2(h2_bits(__floats2half2_rn(x, y)),
                      h2_bits(__floats2half2_rn(z, w)));
}

// ---------------- cp.async helpers ----------------
__device__ __forceinline__ void cp8(void* smem, const void* gmem) {
    uint32_t s = (uint32_t)__cvta_generic_to_shared(smem);
    asm volatile("cp.async.ca.shared.global [%0], [%1], 8;\n" :: "r"(s), "l"(gmem));
}
__device__ __forceinline__ void cp_commit() {
    asm volatile("cp.async.commit_group;\n");
}
template <int N>
__device__ __forceinline__ void cp_wait() {
    asm volatile("cp.async.wait_group %0;\n" :: "n"(N));
}

// =====================================================================
// Input conversion: fp32 -> fp16 for queries/keys/values (one pass).
// =====================================================================
__global__ __launch_bounds__(512)
void conv_inputs(const float4* __restrict__ q, const float4* __restrict__ k,
                 const float4* __restrict__ v,
                 uint2* __restrict__ qh, uint2* __restrict__ kh,
                 uint2* __restrict__ vh)
{
    size_t i = (size_t)blockIdx.x * 512 + threadIdx.x;   // MROWS*DMODEL/4 total
    float4 a = q[i];
    float4 b = k[i];
    float4 c = v[i];
    qh[i] = pack4(a.x, a.y, a.z, a.w);
    kh[i] = pack4(b.x, b.y, b.z, b.w);
    vh[i] = pack4(c.x, c.y, c.z, c.w);
}

// =====================================================================
// Weight prep: Wvo[h*64+o][:] = sum_t Wo[o][h*64+t] * Wv[h*64+t][:]  (half)
//              bvo[h*64+o]    = sum_t Wo[o][h*64+t] * bv[h*64+t]
// plus fp32->fp16 conversion of Wq, Wk.   65536 threads.
// =====================================================================
__global__ __launch_bounds__(256)
void prep_weights(const float* __restrict__ Wo, const float* __restrict__ Wv,
                  const float* __restrict__ bv,
                  const float4* __restrict__ Wq, const float4* __restrict__ Wk,
                  __half* __restrict__ wvoh, float* __restrict__ bvo,
                  uint2* __restrict__ wqh, uint2* __restrict__ wkh)
{
    int idx = blockIdx.x * 256 + threadIdx.x;   // 65536 = 512*512/4
    int n = idx >> 7, i4 = idx & 127;           // n: wvo row, i4: float4 col
    int h = n >> 6, o = n & 63;
    const float* worow = Wo + (size_t)o * DMODEL + h * 64;
    const float4* wv4  = reinterpret_cast<const float4*>(Wv);
    float4 acc = make_float4(0.f, 0.f, 0.f, 0.f);
#pragma unroll 8
    for (int t = 0; t < 64; t++) {
        float w = worow[t];
        float4 x = wv4[(size_t)(h * 64 + t) * 128 + i4];
        acc.x += w * x.x; acc.y += w * x.y; acc.z += w * x.z; acc.w += w * x.w;
    }
    reinterpret_cast<uint2*>(wvoh)[(size_t)n * 128 + i4] =
        pack4(acc.x, acc.y, acc.z, acc.w);

    float4 a = Wq[idx];
    float4 b = Wk[idx];
    wqh[idx] = pack4(a.x, a.y, a.z, a.w);
    wkh[idx] = pack4(b.x, b.y, b.z, b.w);

    if (idx < DMODEL) {
        int h2 = idx >> 6, o2 = idx & 63;
        float s = 0.f;
        for (int t = 0; t < 64; t++)
            s += Wo[(size_t)o2 * DMODEL + h2 * 64 + t] * bv[h2 * 64 + t];
        bvo[idx] = s;
    }
}

// =====================================================================
// fp16 WMMA GEMM (m16n16k16, fp32 accum), 2-stage cp.async pipeline.
//   C[M,512] = A[M,512] @ W[512,512]^T + bias      (A, W in half; C fp32)
// BM=BN=128, BK=32, 512 threads (16 warps, 4x4), 32x32 warp tiles.
// BKP=40 halves (80B rows): conflict-staggered LDSM rows.
// blockIdx.z picks projection {q, k, vo}.
// =====================================================================
#define BKH  32
#define BKP  40

__global__ __launch_bounds__(512, 1)
void qkv_gemm_h(const __half* __restrict__ Aq, const __half* __restrict__ Ak,
                const __half* __restrict__ Av,
                const __half* __restrict__ Wqh, const __half* __restrict__ Wkh,
                const __half* __restrict__ Wvoh,
                const float* __restrict__ bq, const float* __restrict__ bk,
                const float* __restrict__ bvo,
                float* __restrict__ Cq, float* __restrict__ Ck,
                float* __restrict__ Cv)
{
    __shared__ __half As[2][128][BKP];
    __shared__ __half Ws[2][128][BKP];
    float (*stage)[16][20] = reinterpret_cast<float (*)[16][20]>(&As[0][0][0]);

    const int z = blockIdx.z;
    const __half* A    = (z == 0) ? Aq  : (z == 1) ? Ak  : Av;
    const __half* W    = (z == 0) ? Wqh : (z == 1) ? Wkh : Wvoh;
    const float*  bias = (z == 0) ? bq  : (z == 1) ? bk  : bvo;
    float*        C    = (z == 0) ? Cq  : (z == 1) ? Ck  : Cv;

    const int tid  = threadIdx.x;
    const int warp = tid >> 5;
    const int lane = tid & 31;
    const int wm   = warp >> 2;          // 0..3
    const int wn   = warp & 3;           // 0..3
    const int m0   = blockIdx.y * 128;
    const int n0   = blockIdx.x * 128;

    wmma::fragment<wmma::accumulator, 16, 16, 16, float> acc[2][2];
#pragma unroll
    for (int mf = 0; mf < 2; mf++)
#pragma unroll
        for (int nf = 0; nf < 2; nf++)
            wmma::fill_fragment(acc[mf][nf], 0.0f);

    // per-stage loads: each thread covers one row-slice of 8 halves (x2 buffers)
    const int lrow = tid >> 2;           // 0..127
    const int lc   = tid & 3;            // 0..3

    auto issue_stage = [&](int kc, int buf) {
        const __half* Ab = A + (size_t)(m0 + lrow) * DMODEL + kc * BKH;
        const __half* Wb = W + (size_t)(n0 + lrow) * DMODEL + kc * BKH;
        cp8(&As[buf][lrow][lc * 8],     Ab + lc * 8);
        cp8(&As[buf][lrow][lc * 8 + 4], Ab + lc * 8 + 4);
        cp8(&Ws[buf][lrow][lc * 8],     Wb + lc * 8);
        cp8(&Ws[buf][lrow][lc * 8 + 4], Wb + lc * 8 + 4);
        cp_commit();
    };

    issue_stage(0, 0);

    const int nk = DMODEL / BKH;   // 16
    for (int kc = 0; kc < nk; kc++) {
        const int buf = kc & 1;
        if (kc + 1 < nk) { issue_stage(kc + 1, buf ^ 1); cp_wait<1>(); }
        else            { cp_wait<0>(); }
        __syncthreads();

#pragma unroll
        for (int ks = 0; ks < BKH; ks += 16) {
            wmma::fragment<wmma::matrix_a, 16, 16, 16, __half, wmma::row_major> af[2];
            wmma::fragment<wmma::matrix_b, 16, 16, 16, __half, wmma::col_major> bf[2];
#pragma unroll
            for (int mf = 0; mf < 2; mf++)
                wmma::load_matrix_sync(af[mf], &As[buf][wm * 32 + mf * 16][ks], BKP);
#pragma unroll
            for (int nf = 0; nf < 2; nf++)
                wmma::load_matrix_sync(bf[nf], &Ws[buf][wn * 32 + nf * 16][ks], BKP);
#pragma unroll
            for (int mf = 0; mf < 2; mf++)
#pragma unroll
                for (int nf = 0; nf < 2; nf++)
                    wmma::mma_sync(acc[mf][nf], af[mf], bf[nf], acc[mf][nf]);
        }
        __syncthreads();   // also protects stage alias below
    }

    // ---- epilogue: stage fragments (aliased smem), add bias, vector store ----
#pragma unroll
    for (int mf = 0; mf < 2; mf++)
#pragma unroll
        for (int nf = 0; nf < 2; nf++) {
            wmma::store_matrix_sync(&stage[warp][0][0], acc[mf][nf], 20,
                                    wmma::mem_row_major);
            __syncwarp();
            int r  = lane >> 1;
            int c  = (lane & 1) * 8;
            int gm = m0 + wm * 32 + mf * 16 + r;
            int gn = n0 + wn * 32 + nf * 16 + c;
            float4 v0 = *reinterpret_cast<float4*>(&stage[warp][r][c]);
            float4 v1 = *reinterpret_cast<float4*>(&stage[warp][r][c + 4]);
            float4 b0 = *reinterpret_cast<const float4*>(&bias[gn]);
            float4 b1 = *reinterpret_cast<const float4*>(&bias[gn + 4]);
            v0.x += b0.x; v0.y += b0.y; v0.z += b0.z; v0.w += b0.w;
            v1.x += b1.x; v1.y += b1.y; v1.z += b1.z; v1.w += b1.w;
            *reinterpret_cast<float4*>(&C[(size_t)gm * DMODEL + gn])     = v0;
            *reinterpret_cast<float4*>(&C[(size_t)gm * DMODEL + gn + 4]) = v1;
            __syncwarp();
        }
}

// =====================================================================
// Sparse dilated attention, per-batch block, 8 heads sequential,
// accumulating per-head out-projected partials directly into d_out.
//   w_ij = exp(s_ij) - 1 (Chebyshev-1 neighbors);
//   O_i^h = (VOsum^h + sum_j w_ij vo_j^h) / (49 + sum_j w_ij)
//   out_i = sum_h O_i^h + bo      (out dim = 64)
// =====================================================================
__global__ __launch_bounds__(256)
void dilate_attn(const float* __restrict__ q, const float* __restrict__ k,
                 const float* __restrict__ vo, const float* __restrict__ bo,
                 float* __restrict__ out)
{
    __shared__ float4 ta[NSEQ][16];   // q, then vo (reused)
    __shared__ float4 tk[NSEQ][17];   // pad: conflict-free QK dots
    __shared__ float4 outs[NSEQ][16];
    __shared__ float4 vsum[16];
    __shared__ float  wgt[NSEQ][8];
    __shared__ float  zinv[NSEQ];
    __shared__ int    nbr[NSEQ][8];
    __shared__ int    cnt[NSEQ];

    const int b   = blockIdx.x;
    const int tid = threadIdx.x;
    const size_t bbase = (size_t)b * NSEQ * DMODEL;

    if (tid < NSEQ) {
        int r = tid / GRID7, c = tid % GRID7;
        int n = 0;
#pragma unroll
        for (int dr = -1; dr <= 1; dr++)
#pragma unroll
            for (int dc = -1; dc <= 1; dc++) {
                if (dr == 0 && dc == 0) continue;
                int rr = r + dr, cc = c + dc;
                if (rr >= 0 && rr < GRID7 && cc >= 0 && cc < GRID7)
                    nbr[tid][n++] = rr * GRID7 + cc;
            }
        cnt[tid] = n;
        for (int l = n; l < 8; l++) nbr[tid][l] = 0;
    }

    for (int h = 0; h < HEADS; h++) {
        const size_t base4 = (bbase + h * 64) / 4;   // float4 units; row stride 128
        __syncthreads();
        for (int e = tid; e < NSEQ * 16; e += 256) {
            int n = e >> 4, d4 = e & 15;
            ta[n][d4] = reinterpret_cast<const float4*>(q)[base4 + n * 128 + d4];
            tk[n][d4] = reinterpret_cast<const float4*>(k)[base4 + n * 128 + d4];
        }
        __syncthreads();
        for (int t = tid; t < NSEQ * 8; t += 256) {
            int i = t >> 3, l = t & 7;
            float w = 0.f;
            if (l < cnt[i]) {
                int j = nbr[i][l];
                float dot = 0.f;
#pragma unroll
                for (int d4 = 0; d4 < 16; d4++) {
                    float4 a = ta[i][d4], bb = tk[j][d4];
                    dot += a.x * bb.x + a.y * bb.y + a.z * bb.z + a.w * bb.w;
                }
                w = __expf(dot * 0.125f) - 1.f;
            }
            wgt[i][l] = w;
        }
        __syncthreads();
        if (tid < NSEQ) {
            float zz = (float)NSEQ;
#pragma unroll
            for (int l = 0; l < 8; l++) zz += wgt[tid][l];
            zinv[tid] = 1.f / zz;
        }
        for (int e = tid; e < NSEQ * 16; e += 256) {   // vo overwrites q tile
            int n = e >> 4, d4 = e & 15;
            ta[n][d4] = reinterpret_cast<const float4*>(vo)[base4 + n * 128 + d4];
        }
        __syncthreads();
        if (tid >= 224 && tid < 240) {
            int d4 = tid - 224;
            float4 s = make_float4(0.f, 0.f, 0.f, 0.f);
#pragma unroll
            for (int j = 0; j < NSEQ; j++) {
                float4 t = ta[j][d4];
                s.x += t.x; s.y += t.y; s.z += t.z; s.w += t.w;
            }
            vsum[d4] = s;
        }
        __syncthreads();
        for (int e = tid; e < NSEQ * 16; e += 256) {
            int i = e >> 4, d4 = e & 15;
            float4 acc = vsum[d4];
#pragma unroll
            for (int l = 0; l < 8; l++) {
                float w = wgt[i][l];
                float4 vv = ta[nbr[i][l]][d4];
                acc.x += w * vv.x; acc.y += w * vv.y;
                acc.z += w * vv.z; acc.w += w * vv.w;
            }
            float zi = zinv[i];
            acc.x *= zi; acc.y *= zi; acc.z *= zi; acc.w *= zi;
            if (h == 0) {
                float4 bb = reinterpret_cast<const float4*>(bo)[d4];
                acc.x += bb.x; acc.y += bb.y; acc.z += bb.z; acc.w += bb.w;
                outs[i][d4] = acc;
            } else {
                float4 o = outs[i][d4];
                o.x += acc.x; o.y += acc.y; o.z += acc.z; o.w += acc.w;
                outs[i][d4] = o;
            }
        }
    }
    __syncthreads();
    for (int e = tid; e < NSEQ * 16; e += 256) {
        int i = e >> 4, d4 = e & 15;
        reinterpret_cast<float4*>(out)[(size_t)b * NSEQ * 16 + i * 16 + d4] =
            outs[i][d4];
    }
}

// ---------------- launch ----------------
extern "C" void kernel_launch(void* const* d_in, const int* in_sizes, int n_in,
                              void* d_out, int out_size)
{
    const float* queries = (const float*)d_in[0];
    const float* keys    = (const float*)d_in[1];
    const float* values  = (const float*)d_in[2];
    const float* Wq      = (const float*)d_in[3];
    const float* bq      = (const float*)d_in[4];
    const float* Wk      = (const float*)d_in[5];
    const float* bk      = (const float*)d_in[6];
    const float* Wv      = (const float*)d_in[7];
    const float* bv      = (const float*)d_in[8];
    const float* Wo      = (const float*)d_in[9];
    const float* bo      = (const float*)d_in[10];

    float  *q, *k, *vo, *bvo;
    __half *qh, *kh, *vh, *wqh, *wkh, *wvoh;
    cudaGetSymbolAddress((void**)&q,    g_q);
    cudaGetSymbolAddress((void**)&k,    g_k);
    cudaGetSymbolAddress((void**)&vo,   g_vo);
    cudaGetSymbolAddress((void**)&qh,   g_qh);
    cudaGetSymbolAddress((void**)&kh,   g_kh);
    cudaGetSymbolAddress((void**)&vh,   g_vh);
    cudaGetSymbolAddress((void**)&wqh,  g_wqh);
    cudaGetSymbolAddress((void**)&wkh,  g_wkh);
    cudaGetSymbolAddress((void**)&wvoh, g_wvoh);
    cudaGetSymbolAddress((void**)&bvo,  g_bvo);

    // 1) convert inputs fp32 -> fp16
    conv_inputs<<<(MROWS * DMODEL / 4) / 512, 512>>>(
        (const float4*)queries, (const float4*)keys, (const float4*)values,
        (uint2*)qh, (uint2*)kh, (uint2*)vh);

    // 2) fold Wo into Wv (half), convert Wq/Wk to half
    prep_weights<<<256, 256>>>(Wo, Wv, bv, (const float4*)Wq, (const float4*)Wk,
                               wvoh, bvo, (uint2*)wqh, (uint2*)wkh);

    // 3) q/k/vo projections: fp16 tensor cores, fp32 accumulate
    dim3 gridQKV(DMODEL / 128, MTILES, 3);
    qkv_gemm_h<<<gridQKV, 512>>>(qh, kh, vh, wqh, wkh, wvoh,
                                 bq, bk, bvo, q, k, vo);

    // 4) sparse dilated attention + head-summed output, straight to d_out
    dilate_attn<<<BATCH, 256>>>(q, k, vo, bo, (float*)d_out);
}

// round 9
// speedup vs baseline: 3.2381x; 1.0957x over previous
#include <cuda_runtime.h>
#include <cuda_fp16.h>
#include <cstdint>
#include <mma.h>
#include <math.h>

using namespace nvcuda;

#define HEADS   8
#define NSEQ    49
#define GRID7   7
#define DMODEL  512
#define BATCH   2048
#define MROWS   (BATCH * NSEQ)   // 100352 = 784 * 128
#define MTILES  (MROWS / 128)    // 784

// ---------------- scratch (no allocations allowed) ----------------
__device__ float  g_q [(size_t)MROWS * DMODEL];     // q projection (fp32)
__device__ float  g_k [(size_t)MROWS * DMODEL];     // k projection (fp32)
__device__ float  g_vo[(size_t)MROWS * DMODEL];     // vo = values @ Wvo^T (fp32)
__device__ __half g_qh[(size_t)MROWS * DMODEL];     // half copies of inputs
__device__ __half g_kh[(size_t)MROWS * DMODEL];
__device__ __half g_vh[(size_t)MROWS * DMODEL];
__device__ __half g_wqh[DMODEL * DMODEL];
__device__ __half g_wkh[DMODEL * DMODEL];
__device__ __half g_wvoh[DMODEL * DMODEL];
__device__ float  g_bvo[DMODEL];

// ---------------- small helpers ----------------
__device__ __forceinline__ uint32_t h2_bits(__half2 h) {
    union { __half2 h; uint32_t u; } cvt; cvt.h = h; return cvt.u;
}
__device__ __forceinline__ uint2 pack4(float x, float y, float z, float w) {
    return make_uint2(h2_bits(__floats2half2_rn(x, y)),
                      h2_bits(__floats2half2_rn(z, w)));
}

// ---------------- cp.async helpers ----------------
__device__ __forceinline__ void cp16(void* smem, const void* gmem) {
    uint32_t s = (uint32_t)__cvta_generic_to_shared(smem);
    asm volatile("cp.async.cg.shared.global [%0], [%1], 16;\n" :: "r"(s), "l"(gmem));
}
__device__ __forceinline__ void cp_commit() {
    asm volatile("cp.async.commit_group;\n");
}
template <int N>
__device__ __forceinline__ void cp_wait() {
    asm volatile("cp.async.wait_group %0;\n" :: "n"(N));
}

// =====================================================================
// Input conversion: fp32 -> fp16 for queries/keys/values (one pass).
// =====================================================================
__global__ __launch_bounds__(512)
void conv_inputs(const float4* __restrict__ q, const float4* __restrict__ k,
                 const float4* __restrict__ v,
                 uint2* __restrict__ qh, uint2* __restrict__ kh,
                 uint2* __restrict__ vh)
{
    size_t i = (size_t)blockIdx.x * 512 + threadIdx.x;   // MROWS*DMODEL/4 total
    float4 a = q[i];
    float4 b = k[i];
    float4 c = v[i];
    qh[i] = pack4(a.x, a.y, a.z, a.w);
    kh[i] = pack4(b.x, b.y, b.z, b.w);
    vh[i] = pack4(c.x, c.y, c.z, c.w);
}

// =====================================================================
// Weight prep: Wvo[h*64+o][:] = sum_t Wo[o][h*64+t] * Wv[h*64+t][:]  (half)
//              bvo[h*64+o]    = sum_t Wo[o][h*64+t] * bv[h*64+t]
// plus fp32->fp16 conversion of Wq, Wk.
// =====================================================================
__global__ __launch_bounds__(256)
void prep_weights(const float* __restrict__ Wo, const float* __restrict__ Wv,
                  const float* __restrict__ bv,
                  const float4* __restrict__ Wq, const float4* __restrict__ Wk,
                  __half* __restrict__ wvoh, float* __restrict__ bvo,
                  uint2* __restrict__ wqh, uint2* __restrict__ wkh)
{
    int idx = blockIdx.x * 256 + threadIdx.x;   // 65536 = 512*512/4
    int n = idx >> 7, i4 = idx & 127;
    int h = n >> 6, o = n & 63;
    const float* worow = Wo + (size_t)o * DMODEL + h * 64;
    const float4* wv4  = reinterpret_cast<const float4*>(Wv);
    float4 acc = make_float4(0.f, 0.f, 0.f, 0.f);
#pragma unroll 8
    for (int t = 0; t < 64; t++) {
        float w = worow[t];
        float4 x = wv4[(size_t)(h * 64 + t) * 128 + i4];
        acc.x += w * x.x; acc.y += w * x.y; acc.z += w * x.z; acc.w += w * x.w;
    }
    reinterpret_cast<uint2*>(wvoh)[(size_t)n * 128 + i4] =
        pack4(acc.x, acc.y, acc.z, acc.w);

    float4 a = Wq[idx];
    float4 b = Wk[idx];
    wqh[idx] = pack4(a.x, a.y, a.z, a.w);
    wkh[idx] = pack4(b.x, b.y, b.z, b.w);

    if (idx < DMODEL) {
        int h2 = idx >> 6, o2 = idx & 63;
        float s = 0.f;
        for (int t = 0; t < 64; t++)
            s += Wo[(size_t)o2 * DMODEL + h2 * 64 + t] * bv[h2 * 64 + t];
        bvo[idx] = s;
    }
}

// =====================================================================
// fp16 WMMA GEMM (m16n16k16, fp32 accum), 4-stage cp.async pipeline.
//   C[M,512] = A[M,512] @ W[512,512]^T + bias
// BM=BN=128, BK=32, 512 threads (16 warps, 4x4), 32x32 warp tiles.
// One 16B cp.async.cg per thread per tile; prefetch depth 3.
// blockIdx.z picks projection {q, k, vo}.
// =====================================================================
#define BKH     32
#define BKP     40
#define STAGES  4
#define STAGE_BYTES (128 * BKP * 2)                    // 10240
#define GEMM_SMEM   (2 * STAGES * STAGE_BYTES)         // 81920

__global__ __launch_bounds__(512, 1)
void qkv_gemm_h(const __half* __restrict__ Aq, const __half* __restrict__ Ak,
                const __half* __restrict__ Av,
                const __half* __restrict__ Wqh, const __half* __restrict__ Wkh,
                const __half* __restrict__ Wvoh,
                const float* __restrict__ bq, const float* __restrict__ bk,
                const float* __restrict__ bvo,
                float* __restrict__ Cq, float* __restrict__ Ck,
                float* __restrict__ Cv)
{
    extern __shared__ __align__(16) unsigned char dynsmem[];
    __half (*As)[128][BKP] =
        reinterpret_cast<__half (*)[128][BKP]>(dynsmem);
    __half (*Ws)[128][BKP] =
        reinterpret_cast<__half (*)[128][BKP]>(dynsmem + STAGES * STAGE_BYTES);
    float (*stage)[16][20] = reinterpret_cast<float (*)[16][20]>(dynsmem);

    const int z = blockIdx.z;
    const __half* A    = (z == 0) ? Aq  : (z == 1) ? Ak  : Av;
    const __half* W    = (z == 0) ? Wqh : (z == 1) ? Wkh : Wvoh;
    const float*  bias = (z == 0) ? bq  : (z == 1) ? bk  : bvo;
    float*        C    = (z == 0) ? Cq  : (z == 1) ? Ck  : Cv;

    const int tid  = threadIdx.x;
    const int warp = tid >> 5;
    const int lane = tid & 31;
    const int wm   = warp >> 2;          // 0..3
    const int wn   = warp & 3;           // 0..3
    const int m0   = blockIdx.y * 128;
    const int n0   = blockIdx.x * 128;

    wmma::fragment<wmma::accumulator, 16, 16, 16, float> acc[2][2];
#pragma unroll
    for (int mf = 0; mf < 2; mf++)
#pragma unroll
        for (int nf = 0; nf < 2; nf++)
            wmma::fill_fragment(acc[mf][nf], 0.0f);

    // loads: 128 rows x 64B per tile; 4 threads/row, one cp16 each (A and W)
    const int lrow = tid >> 2;           // 0..127
    const int lc   = tid & 3;            // 0..3

    auto issue_stage = [&](int kc, int s) {
        cp16(&As[s][lrow][lc * 8],
             A + (size_t)(m0 + lrow) * DMODEL + kc * BKH + lc * 8);
        cp16(&Ws[s][lrow][lc * 8],
             W + (size_t)(n0 + lrow) * DMODEL + kc * BKH + lc * 8);
        cp_commit();
    };

    const int nk = DMODEL / BKH;   // 16
    issue_stage(0, 0);
    issue_stage(1, 1);
    issue_stage(2, 2);

    for (int kc = 0; kc < nk; kc++) {
        if (kc + 3 < nk) issue_stage(kc + 3, (kc + 3) & 3);
        else             cp_commit();        // keep group count uniform
        cp_wait<3>();                        // group kc complete
        __syncthreads();

        const int buf = kc & 3;
#pragma unroll
        for (int ks = 0; ks < BKH; ks += 16) {
            wmma::fragment<wmma::matrix_a, 16, 16, 16, __half, wmma::row_major> af[2];
            wmma::fragment<wmma::matrix_b, 16, 16, 16, __half, wmma::col_major> bf[2];
#pragma unroll
            for (int mf = 0; mf < 2; mf++)
                wmma::load_matrix_sync(af[mf], &As[buf][wm * 32 + mf * 16][ks], BKP);
#pragma unroll
            for (int nf = 0; nf < 2; nf++)
                wmma::load_matrix_sync(bf[nf], &Ws[buf][wn * 32 + nf * 16][ks], BKP);
#pragma unroll
            for (int mf = 0; mf < 2; mf++)
#pragma unroll
                for (int nf = 0; nf < 2; nf++)
                    wmma::mma_sync(acc[mf][nf], af[mf], bf[nf], acc[mf][nf]);
        }
        __syncthreads();   // stage reuse fence (also protects epilogue alias)
    }

    // ---- epilogue: stage fragments (aliased smem), add bias, vector store ----
#pragma unroll
    for (int mf = 0; mf < 2; mf++)
#pragma unroll
        for (int nf = 0; nf < 2; nf++) {
            wmma::store_matrix_sync(&stage[warp][0][0], acc[mf][nf], 20,
                                    wmma::mem_row_major);
            __syncwarp();
            int r  = lane >> 1;
            int c  = (lane & 1) * 8;
            int gm = m0 + wm * 32 + mf * 16 + r;
            int gn = n0 + wn * 32 + nf * 16 + c;
            float4 v0 = *reinterpret_cast<float4*>(&stage[warp][r][c]);
            float4 v1 = *reinterpret_cast<float4*>(&stage[warp][r][c + 4]);
            float4 b0 = *reinterpret_cast<const float4*>(&bias[gn]);
            float4 b1 = *reinterpret_cast<const float4*>(&bias[gn + 4]);
            v0.x += b0.x; v0.y += b0.y; v0.z += b0.z; v0.w += b0.w;
            v1.x += b1.x; v1.y += b1.y; v1.z += b1.z; v1.w += b1.w;
            *reinterpret_cast<float4*>(&C[(size_t)gm * DMODEL + gn])     = v0;
            *reinterpret_cast<float4*>(&C[(size_t)gm * DMODEL + gn + 4]) = v1;
            __syncwarp();
        }
}

// =====================================================================
// Sparse dilated attention: one block per batch, 512 threads as TWO
// 256-thread groups, each owning one head per iteration (4 iterations
// cover 8 heads). Per-head out-projected partials accumulate in smem;
// groups merge at the end.  (mask algebra: w = exp(s)-1 on the <=8
// Chebyshev-1 neighbors; O = (Vsum + sum w*vo) / (49 + sum w))
// =====================================================================
struct AttnSmem {
    float4 ta[2][NSEQ][16];    // q tile, then vo tile (reused)
    float4 tk[2][NSEQ][17];    // padded: conflict-staggered QK reads
    float4 outs[2][NSEQ][16];  // per-group output accumulators
    float4 vsum[2][16];
    float  wgt[2][NSEQ][8];
    float  zinv[2][NSEQ];
    int    nbr[NSEQ][8];
    int    cnt[NSEQ];
};
#define ATTN_SMEM ((int)sizeof(AttnSmem))

__global__ __launch_bounds__(512)
void dilate_attn(const float* __restrict__ q, const float* __restrict__ k,
                 const float* __restrict__ vo, const float* __restrict__ bo,
                 float* __restrict__ out)
{
    extern __shared__ __align__(16) unsigned char asmem[];
    AttnSmem* S = reinterpret_cast<AttnSmem*>(asmem);

    const int b   = blockIdx.x;
    const int tid = threadIdx.x;
    const int g   = tid >> 8;        // head group 0/1
    const int lt  = tid & 255;       // lane within group
    const size_t bbase = (size_t)b * NSEQ * DMODEL;

    if (tid < NSEQ) {
        int r = tid / GRID7, c = tid % GRID7;
        int n = 0;
#pragma unroll
        for (int dr = -1; dr <= 1; dr++)
#pragma unroll
            for (int dc = -1; dc <= 1; dc++) {
                if (dr == 0 && dc == 0) continue;
                int rr = r + dr, cc = c + dc;
                if (rr >= 0 && rr < GRID7 && cc >= 0 && cc < GRID7)
                    S->nbr[tid][n++] = rr * GRID7 + cc;
            }
        S->cnt[tid] = n;
        for (int l = n; l < 8; l++) S->nbr[tid][l] = 0;
    }

    for (int hh = 0; hh < HEADS / 2; hh++) {
        const int h = hh * 2 + g;
        const size_t base4 = (bbase + h * 64) / 4;   // float4 units; stride 128
        __syncthreads();
        for (int e = lt; e < NSEQ * 16; e += 256) {
            int n = e >> 4, d4 = e & 15;
            S->ta[g][n][d4] = reinterpret_cast<const float4*>(q)[base4 + n * 128 + d4];
            S->tk[g][n][d4] = reinterpret_cast<const float4*>(k)[base4 + n * 128 + d4];
        }
        __syncthreads();
        for (int t = lt; t < NSEQ * 8; t += 256) {
            int i = t >> 3, l = t & 7;
            float w = 0.f;
            if (l < S->cnt[i]) {
                int j = S->nbr[i][l];
                float dot = 0.f;
#pragma unroll
                for (int d4 = 0; d4 < 16; d4++) {
                    float4 a = S->ta[g][i][d4], bb = S->tk[g][j][d4];
                    dot += a.x * bb.x + a.y * bb.y + a.z * bb.z + a.w * bb.w;
                }
                w = __expf(dot * 0.125f) - 1.f;
            }
            S->wgt[g][i][l] = w;
        }
        __syncthreads();
        if (lt < NSEQ) {
            float zz = (float)NSEQ;
#pragma unroll
            for (int l = 0; l < 8; l++) zz += S->wgt[g][lt][l];
            S->zinv[g][lt] = 1.f / zz;
        }
        for (int e = lt; e < NSEQ * 16; e += 256) {   // vo overwrites q tile
            int n = e >> 4, d4 = e & 15;
            S->ta[g][n][d4] = reinterpret_cast<const float4*>(vo)[base4 + n * 128 + d4];
        }
        __syncthreads();
        if (lt >= 224 && lt < 240) {
            int d4 = lt - 224;
            float4 s = make_float4(0.f, 0.f, 0.f, 0.f);
#pragma unroll
            for (int j = 0; j < NSEQ; j++) {
                float4 t = S->ta[g][j][d4];
                s.x += t.x; s.y += t.y; s.z += t.z; s.w += t.w;
            }
            S->vsum[g][d4] = s;
        }
        __syncthreads();
        for (int e = lt; e < NSEQ * 16; e += 256) {
            int i = e >> 4, d4 = e & 15;
            float4 acc = S->vsum[g][d4];
#pragma unroll
            for (int l = 0; l < 8; l++) {
                float w = S->wgt[g][i][l];
                float4 vv = S->ta[g][S->nbr[i][l]][d4];
                acc.x += w * vv.x; acc.y += w * vv.y;
                acc.z += w * vv.z; acc.w += w * vv.w;
            }
            float zi = S->zinv[g][i];
            acc.x *= zi; acc.y *= zi; acc.z *= zi; acc.w *= zi;
            if (hh == 0) {
                S->outs[g][i][d4] = acc;
            } else {
                float4 o = S->outs[g][i][d4];
                o.x += acc.x; o.y += acc.y; o.z += acc.z; o.w += acc.w;
                S->outs[g][i][d4] = o;
            }
        }
    }
    __syncthreads();
    for (int e = tid; e < NSEQ * 16; e += 512) {
        int i = e >> 4, d4 = e & 15;
        float4 o0 = S->outs[0][i][d4];
        float4 o1 = S->outs[1][i][d4];
        float4 bb = reinterpret_cast<const float4*>(bo)[d4];
        o0.x += o1.x + bb.x; o0.y += o1.y + bb.y;
        o0.z += o1.z + bb.z; o0.w += o1.w + bb.w;
        reinterpret_cast<float4*>(out)[(size_t)b * NSEQ * 16 + i * 16 + d4] = o0;
    }
}

// ---------------- launch ----------------
extern "C" void kernel_launch(void* const* d_in, const int* in_sizes, int n_in,
                              void* d_out, int out_size)
{
    const float* queries = (const float*)d_in[0];
    const float* keys    = (const float*)d_in[1];
    const float* values  = (const float*)d_in[2];
    const float* Wq      = (const float*)d_in[3];
    const float* bq      = (const float*)d_in[4];
    const float* Wk      = (const float*)d_in[5];
    const float* bk      = (const float*)d_in[6];
    const float* Wv      = (const float*)d_in[7];
    const float* bv      = (const float*)d_in[8];
    const float* Wo      = (const float*)d_in[9];
    const float* bo      = (const float*)d_in[10];

    float  *q, *k, *vo, *bvo;
    __half *qh, *kh, *vh, *wqh, *wkh, *wvoh;
    cudaGetSymbolAddress((void**)&q,    g_q);
    cudaGetSymbolAddress((void**)&k,    g_k);
    cudaGetSymbolAddress((void**)&vo,   g_vo);
    cudaGetSymbolAddress((void**)&qh,   g_qh);
    cudaGetSymbolAddress((void**)&kh,   g_kh);
    cudaGetSymbolAddress((void**)&vh,   g_vh);
    cudaGetSymbolAddress((void**)&wqh,  g_wqh);
    cudaGetSymbolAddress((void**)&wkh,  g_wkh);
    cudaGetSymbolAddress((void**)&wvoh, g_wvoh);
    cudaGetSymbolAddress((void**)&bvo,  g_bvo);

    cudaFuncSetAttribute(qkv_gemm_h,
                         cudaFuncAttributeMaxDynamicSharedMemorySize, GEMM_SMEM);
    cudaFuncSetAttribute(dilate_attn,
                         cudaFuncAttributeMaxDynamicSharedMemorySize, ATTN_SMEM);

    // 1) convert inputs fp32 -> fp16
    conv_inputs<<<(MROWS * DMODEL / 4) / 512, 512>>>(
        (const float4*)queries, (const float4*)keys, (const float4*)values,
        (uint2*)qh, (uint2*)kh, (uint2*)vh);

    // 2) fold Wo into Wv (half), convert Wq/Wk to half
    prep_weights<<<256, 256>>>(Wo, Wv, bv, (const float4*)Wq, (const float4*)Wk,
                               wvoh, bvo, (uint2*)wqh, (uint2*)wkh);

    // 3) q/k/vo projections: fp16 tensor cores, fp32 accumulate
    dim3 gridQKV(DMODEL / 128, MTILES, 3);
    qkv_gemm_h<<<gridQKV, 512, GEMM_SMEM>>>(qh, kh, vh, wqh, wkh, wvoh,
                                            bq, bk, bvo, q, k, vo);

    // 4) sparse dilated attention + head-summed output, straight to d_out
    dilate_attn<<<BATCH, 512, ATTN_SMEM>>>(q, k, vo, bo, (float*)d_out);
}

// round 10
// speedup vs baseline: 4.0754x; 1.2586x over previous
#include <cuda_runtime.h>
#include <cuda_fp16.h>
#include <cstdint>
#include <mma.h>
#include <math.h>

using namespace nvcuda;

#define HEADS   8
#define NSEQ    49
#define GRID7   7
#define DMODEL  512
#define BATCH   2048
#define MROWS   (BATCH * NSEQ)   // 100352 = 392 * 256
#define MTILES  (MROWS / 256)    // 392

// ---------------- scratch (no allocations allowed) ----------------
__device__ __half g_qh [(size_t)MROWS * DMODEL];    // half inputs (GEMM A)
__device__ __half g_kh [(size_t)MROWS * DMODEL];
__device__ __half g_vh [(size_t)MROWS * DMODEL];
__device__ __half g_qph[(size_t)MROWS * DMODEL];    // q projection (half)
__device__ __half g_kph[(size_t)MROWS * DMODEL];    // k projection (half)
__device__ float  g_vo [(size_t)MROWS * DMODEL];    // vo projection (fp32)
__device__ __half g_wqh[DMODEL * DMODEL];
__device__ __half g_wkh[DMODEL * DMODEL];
__device__ __half g_wvoh[DMODEL * DMODEL];
__device__ float  g_bvo[DMODEL];

// ---------------- small helpers ----------------
__device__ __forceinline__ uint32_t h2_bits(__half2 h) {
    union { __half2 h; uint32_t u; } cvt; cvt.h = h; return cvt.u;
}
__device__ __forceinline__ uint2 pack4(float x, float y, float z, float w) {
    return make_uint2(h2_bits(__floats2half2_rn(x, y)),
                      h2_bits(__floats2half2_rn(z, w)));
}
__device__ __forceinline__ float hmulsum(uint32_t a, uint32_t b) {
    __half2 ha = *reinterpret_cast<__half2*>(&a);
    __half2 hb = *reinterpret_cast<__half2*>(&b);
    float2 fa = __half22float2(ha);
    float2 fb = __half22float2(hb);
    return fa.x * fb.x + fa.y * fb.y;
}

// ---------------- cp.async helpers ----------------
__device__ __forceinline__ void cp16(void* smem, const void* gmem) {
    uint32_t s = (uint32_t)__cvta_generic_to_shared(smem);
    asm volatile("cp.async.cg.shared.global [%0], [%1], 16;\n" :: "r"(s), "l"(gmem));
}
__device__ __forceinline__ void cp_commit() {
    asm volatile("cp.async.commit_group;\n");
}
template <int N>
__device__ __forceinline__ void cp_wait() {
    asm volatile("cp.async.wait_group %0;\n" :: "n"(N));
}

// =====================================================================
// Input conversion: fp32 -> fp16 for queries/keys/values (one pass).
// =====================================================================
__global__ __launch_bounds__(512)
void conv_inputs(const float4* __restrict__ q, const float4* __restrict__ k,
                 const float4* __restrict__ v,
                 uint2* __restrict__ qh, uint2* __restrict__ kh,
                 uint2* __restrict__ vh)
{
    size_t i = (size_t)blockIdx.x * 512 + threadIdx.x;
    float4 a = q[i];
    float4 b = k[i];
    float4 c = v[i];
    qh[i] = pack4(a.x, a.y, a.z, a.w);
    kh[i] = pack4(b.x, b.y, b.z, b.w);
    vh[i] = pack4(c.x, c.y, c.z, c.w);
}

// =====================================================================
// Weight prep: Wvo = per-head Wo_h @ Wv_h (half), bvo; Wq/Wk -> half.
// =====================================================================
__global__ __launch_bounds__(256)
void prep_weights(const float* __restrict__ Wo, const float* __restrict__ Wv,
                  const float* __restrict__ bv,
                  const float4* __restrict__ Wq, const float4* __restrict__ Wk,
                  __half* __restrict__ wvoh, float* __restrict__ bvo,
                  uint2* __restrict__ wqh, uint2* __restrict__ wkh)
{
    int idx = blockIdx.x * 256 + threadIdx.x;   // 65536 = 512*512/4
    int n = idx >> 7, i4 = idx & 127;
    int h = n >> 6, o = n & 63;
    const float* worow = Wo + (size_t)o * DMODEL + h * 64;
    const float4* wv4  = reinterpret_cast<const float4*>(Wv);
    float4 acc = make_float4(0.f, 0.f, 0.f, 0.f);
#pragma unroll 8
    for (int t = 0; t < 64; t++) {
        float w = worow[t];
        float4 x = wv4[(size_t)(h * 64 + t) * 128 + i4];
        acc.x += w * x.x; acc.y += w * x.y; acc.z += w * x.z; acc.w += w * x.w;
    }
    reinterpret_cast<uint2*>(wvoh)[(size_t)n * 128 + i4] =
        pack4(acc.x, acc.y, acc.z, acc.w);

    float4 a = Wq[idx];
    float4 b = Wk[idx];
    wqh[idx] = pack4(a.x, a.y, a.z, a.w);
    wkh[idx] = pack4(b.x, b.y, b.z, b.w);

    if (idx < DMODEL) {
        int h2 = idx >> 6, o2 = idx & 63;
        float s = 0.f;
        for (int t = 0; t < 64; t++)
            s += Wo[(size_t)o2 * DMODEL + h2 * 64 + t] * bv[h2 * 64 + t];
        bvo[idx] = s;
    }
}

// =====================================================================
// fp16 WMMA GEMM, 4-stage cp.async pipeline, 64x32 warp tiles.
//   C[M,512] = A[M,512] @ W[512,512]^T + bias
// BM=256, BN=128, BK=32, 512 threads (16 warps, 4x4).
// z in {0,1}: C written as fp16 (q, k); z==2: fp32 (vo).
// =====================================================================
#define BKH     32
#define BKP     40
#define STAGES  4
#define A_STAGE (256 * BKP * 2)                     // 20480
#define W_STAGE (128 * BKP * 2)                     // 10240
#define GEMM_SMEM (STAGES * (A_STAGE + W_STAGE))    // 122880

__global__ __launch_bounds__(512, 1)
void qkv_gemm_h(const __half* __restrict__ Aq, const __half* __restrict__ Ak,
                const __half* __restrict__ Av,
                const __half* __restrict__ Wqh, const __half* __restrict__ Wkh,
                const __half* __restrict__ Wvoh,
                const float* __restrict__ bq, const float* __restrict__ bk,
                const float* __restrict__ bvo,
                __half* __restrict__ Cq, __half* __restrict__ Ck,
                float* __restrict__ Cv)
{
    extern __shared__ __align__(16) unsigned char dynsmem[];
    __half (*As)[256][BKP] =
        reinterpret_cast<__half (*)[256][BKP]>(dynsmem);
    __half (*Ws)[128][BKP] =
        reinterpret_cast<__half (*)[128][BKP]>(dynsmem + STAGES * A_STAGE);
    float (*stage)[16][20] = reinterpret_cast<float (*)[16][20]>(dynsmem);

    const int z = blockIdx.z;
    const __half* A    = (z == 0) ? Aq  : (z == 1) ? Ak  : Av;
    const __half* W    = (z == 0) ? Wqh : (z == 1) ? Wkh : Wvoh;
    const float*  bias = (z == 0) ? bq  : (z == 1) ? bk  : bvo;
    __half* Ch = (z == 0) ? Cq : Ck;

    const int tid  = threadIdx.x;
    const int warp = tid >> 5;
    const int lane = tid & 31;
    const int wm   = warp >> 2;          // 0..3 -> 64 rows each
    const int wn   = warp & 3;           // 0..3 -> 32 cols each
    const int m0   = blockIdx.y * 256;
    const int n0   = blockIdx.x * 128;

    wmma::fragment<wmma::accumulator, 16, 16, 16, float> acc[4][2];
#pragma unroll
    for (int mf = 0; mf < 4; mf++)
#pragma unroll
        for (int nf = 0; nf < 2; nf++)
            wmma::fill_fragment(acc[mf][nf], 0.0f);

    auto issue_stage = [&](int kc, int s) {
#pragma unroll
        for (int r = 0; r < 2; r++) {            // A: 1024 cp16
            int idx = tid + r * 512;
            int row = idx >> 2, lc = idx & 3;
            cp16(&As[s][row][lc * 8],
                 A + (size_t)(m0 + row) * DMODEL + kc * BKH + lc * 8);
        }
        {                                        // W: 512 cp16
            int row = tid >> 2, lc = tid & 3;
            cp16(&Ws[s][row][lc * 8],
                 W + (size_t)(n0 + row) * DMODEL + kc * BKH + lc * 8);
        }
        cp_commit();
    };

    const int nk = DMODEL / BKH;   // 16
    issue_stage(0, 0);
    issue_stage(1, 1);
    issue_stage(2, 2);

    for (int kc = 0; kc < nk; kc++) {
        if (kc + 3 < nk) issue_stage(kc + 3, (kc + 3) & 3);
        else             cp_commit();
        cp_wait<3>();
        __syncthreads();

        const int buf = kc & 3;
#pragma unroll
        for (int ks = 0; ks < BKH; ks += 16) {
            wmma::fragment<wmma::matrix_b, 16, 16, 16, __half, wmma::col_major> bf[2];
#pragma unroll
            for (int nf = 0; nf < 2; nf++)
                wmma::load_matrix_sync(bf[nf], &Ws[buf][wn * 32 + nf * 16][ks], BKP);
#pragma unroll
            for (int mf = 0; mf < 4; mf++) {
                wmma::fragment<wmma::matrix_a, 16, 16, 16, __half, wmma::row_major> af;
                wmma::load_matrix_sync(af, &As[buf][wm * 64 + mf * 16][ks], BKP);
#pragma unroll
                for (int nf = 0; nf < 2; nf++)
                    wmma::mma_sync(acc[mf][nf], af, bf[nf], acc[mf][nf]);
            }
        }
        __syncthreads();
    }

    // ---- epilogue: stage fragments (aliased smem), bias, store ----
#pragma unroll
    for (int mf = 0; mf < 4; mf++)
#pragma unroll
        for (int nf = 0; nf < 2; nf++) {
            wmma::store_matrix_sync(&stage[warp][0][0], acc[mf][nf], 20,
                                    wmma::mem_row_major);
            __syncwarp();
            int r  = lane >> 1;
            int c  = (lane & 1) * 8;
            int gm = m0 + wm * 64 + mf * 16 + r;
            int gn = n0 + wn * 32 + nf * 16 + c;
            float4 v0 = *reinterpret_cast<float4*>(&stage[warp][r][c]);
            float4 v1 = *reinterpret_cast<float4*>(&stage[warp][r][c + 4]);
            float4 b0 = *reinterpret_cast<const float4*>(&bias[gn]);
            float4 b1 = *reinterpret_cast<const float4*>(&bias[gn + 4]);
            v0.x += b0.x; v0.y += b0.y; v0.z += b0.z; v0.w += b0.w;
            v1.x += b1.x; v1.y += b1.y; v1.z += b1.z; v1.w += b1.w;
            if (z < 2) {
                uint2 p0 = pack4(v0.x, v0.y, v0.z, v0.w);
                uint2 p1 = pack4(v1.x, v1.y, v1.z, v1.w);
                *reinterpret_cast<uint4*>(&Ch[(size_t)gm * DMODEL + gn]) =
                    make_uint4(p0.x, p0.y, p1.x, p1.y);
            } else {
                *reinterpret_cast<float4*>(&Cv[(size_t)gm * DMODEL + gn])     = v0;
                *reinterpret_cast<float4*>(&Cv[(size_t)gm * DMODEL + gn + 4]) = v1;
            }
            __syncwarp();
        }
}

// =====================================================================
// Sparse dilated attention. One block per batch, 256 threads, 8 heads
// sequential. q/k tiles in fp16 (half LDS traffic), vo in fp32.
//   w_ij = exp(s_ij) - 1 on Chebyshev-1 neighbors;
//   O_i  = (VOsum + sum w_ij vo_j) / (49 + sum w_ij); out = sum_h O + bo
// =====================================================================
__global__ __launch_bounds__(256)
void dilate_attn(const __half* __restrict__ qh, const __half* __restrict__ kh,
                 const float* __restrict__ vo, const float* __restrict__ bo,
                 float* __restrict__ out)
{
    __shared__ uint4  tq[NSEQ][9];     // 64 halves/row (8 used; +1 pad)
    __shared__ uint4  tk[NSEQ][9];
    __shared__ float4 tvo[NSEQ][17];   // 16 used; +1 pad
    __shared__ float4 outs[NSEQ][16];
    __shared__ float4 vsum[16];
    __shared__ float  wgt[NSEQ][8];
    __shared__ float  zinv[NSEQ];
    __shared__ int    nbr[NSEQ][8];
    __shared__ int    cnt[NSEQ];

    const int b   = blockIdx.x;
    const int tid = threadIdx.x;
    const size_t bbase = (size_t)b * NSEQ * DMODEL;   // element units

    if (tid < NSEQ) {
        int r = tid / GRID7, c = tid % GRID7;
        int n = 0;
#pragma unroll
        for (int dr = -1; dr <= 1; dr++)
#pragma unroll
            for (int dc = -1; dc <= 1; dc++) {
                if (dr == 0 && dc == 0) continue;
                int rr = r + dr, cc = c + dc;
                if (rr >= 0 && rr < GRID7 && cc >= 0 && cc < GRID7)
                    nbr[tid][n++] = rr * GRID7 + cc;
            }
        cnt[tid] = n;
        for (int l = n; l < 8; l++) nbr[tid][l] = 0;
    }

    for (int h = 0; h < HEADS; h++) {
        const size_t base8 = (bbase + h * 64) / 8;    // uint4 units (halves)
        const size_t base4 = (bbase + h * 64) / 4;    // float4 units
        __syncthreads();
        // ---- load all tiles ----
        for (int e = tid; e < NSEQ * 8; e += 256) {
            int n = e >> 3, d8 = e & 7;
            tq[n][d8] = reinterpret_cast<const uint4*>(qh)[base8 + n * 64 + d8];
            tk[n][d8] = reinterpret_cast<const uint4*>(kh)[base8 + n * 64 + d8];
        }
        for (int e = tid; e < NSEQ * 16; e += 256) {
            int n = e >> 4, d4 = e & 15;
            tvo[n][d4] = reinterpret_cast<const float4*>(vo)[base4 + n * 128 + d4];
        }
        __syncthreads();
        // ---- sparse QK dots (fp16 tiles, fp32 math) ----
        for (int t = tid; t < NSEQ * 8; t += 256) {
            int i = t >> 3, l = t & 7;
            float w = 0.f;
            if (l < cnt[i]) {
                int j = nbr[i][l];
                float dot = 0.f;
#pragma unroll
                for (int d8 = 0; d8 < 8; d8++) {
                    uint4 a = tq[i][d8], bb = tk[j][d8];
                    dot += hmulsum(a.x, bb.x) + hmulsum(a.y, bb.y)
                         + hmulsum(a.z, bb.z) + hmulsum(a.w, bb.w);
                }
                w = __expf(dot * 0.125f) - 1.f;
            }
            wgt[i][l] = w;
        }
        __syncthreads();
        // ---- normalizers + vo column sums ----
        if (tid < NSEQ) {
            float zz = (float)NSEQ;
#pragma unroll
            for (int l = 0; l < 8; l++) zz += wgt[tid][l];
            zinv[tid] = 1.f / zz;
        }
        if (tid >= 64 && tid < 80) {
            int d4 = tid - 64;
            float4 s = make_float4(0.f, 0.f, 0.f, 0.f);
#pragma unroll
            for (int j = 0; j < NSEQ; j++) {
                float4 t = tvo[j][d4];
                s.x += t.x; s.y += t.y; s.z += t.z; s.w += t.w;
            }
            vsum[d4] = s;
        }
        __syncthreads();
        // ---- output accumulate ----
        for (int e = tid; e < NSEQ * 16; e += 256) {
            int i = e >> 4, d4 = e & 15;
            float4 acc = vsum[d4];
#pragma unroll
            for (int l = 0; l < 8; l++) {
                float w = wgt[i][l];
                float4 vv = tvo[nbr[i][l]][d4];
                acc.x += w * vv.x; acc.y += w * vv.y;
                acc.z += w * vv.z; acc.w += w * vv.w;
            }
            float zi = zinv[i];
            acc.x *= zi; acc.y *= zi; acc.z *= zi; acc.w *= zi;
            if (h == 0) {
                float4 bb = reinterpret_cast<const float4*>(bo)[d4];
                acc.x += bb.x; acc.y += bb.y; acc.z += bb.z; acc.w += bb.w;
                outs[i][d4] = acc;
            } else {
                float4 o = outs[i][d4];
                o.x += acc.x; o.y += acc.y; o.z += acc.z; o.w += acc.w;
                outs[i][d4] = o;
            }
        }
    }
    __syncthreads();
    for (int e = tid; e < NSEQ * 16; e += 256) {
        int i = e >> 4, d4 = e & 15;
        reinterpret_cast<float4*>(out)[(size_t)b * NSEQ * 16 + i * 16 + d4] =
            outs[i][d4];
    }
}

// ---------------- launch ----------------
extern "C" void kernel_launch(void* const* d_in, const int* in_sizes, int n_in,
                              void* d_out, int out_size)
{
    const float* queries = (const float*)d_in[0];
    const float* keys    = (const float*)d_in[1];
    const float* values  = (const float*)d_in[2];
    const float* Wq      = (const float*)d_in[3];
    const float* bq      = (const float*)d_in[4];
    const float* Wk      = (const float*)d_in[5];
    const float* bk      = (const float*)d_in[6];
    const float* Wv      = (const float*)d_in[7];
    const float* bv      = (const float*)d_in[8];
    const float* Wo      = (const float*)d_in[9];
    const float* bo      = (const float*)d_in[10];

    float  *vo, *bvo;
    __half *qh, *kh, *vh, *qph, *kph, *wqh, *wkh, *wvoh;
    cudaGetSymbolAddress((void**)&qh,   g_qh);
    cudaGetSymbolAddress((void**)&kh,   g_kh);
    cudaGetSymbolAddress((void**)&vh,   g_vh);
    cudaGetSymbolAddress((void**)&qph,  g_qph);
    cudaGetSymbolAddress((void**)&kph,  g_kph);
    cudaGetSymbolAddress((void**)&vo,   g_vo);
    cudaGetSymbolAddress((void**)&wqh,  g_wqh);
    cudaGetSymbolAddress((void**)&wkh,  g_wkh);
    cudaGetSymbolAddress((void**)&wvoh, g_wvoh);
    cudaGetSymbolAddress((void**)&bvo,  g_bvo);

    cudaFuncSetAttribute(qkv_gemm_h,
                         cudaFuncAttributeMaxDynamicSharedMemorySize, GEMM_SMEM);

    // 1) convert inputs fp32 -> fp16
    conv_inputs<<<(MROWS * DMODEL / 4) / 512, 512>>>(
        (const float4*)queries, (const float4*)keys, (const float4*)values,
        (uint2*)qh, (uint2*)kh, (uint2*)vh);

    // 2) fold Wo into Wv (half), convert Wq/Wk to half
    prep_weights<<<256, 256>>>(Wo, Wv, bv, (const float4*)Wq, (const float4*)Wk,
                               wvoh, bvo, (uint2*)wqh, (uint2*)wkh);

    // 3) projections: q,k -> fp16; vo -> fp32
    dim3 gridQKV(DMODEL / 128, MTILES, 3);
    qkv_gemm_h<<<gridQKV, 512, GEMM_SMEM>>>(qh, kh, vh, wqh, wkh, wvoh,
                                            bq, bk, bvo, qph, kph, vo);

    // 4) sparse dilated attention + head-summed output, straight to d_out
    dilate_attn<<<BATCH, 256>>>(qph, kph, vo, bo, (float*)d_out);
}

// round 11
// speedup vs baseline: 4.6876x; 1.1502x over previous
#include <cuda_runtime.h>
#include <cuda_fp16.h>
#include <cstdint>
#include <mma.h>
#include <math.h>

using namespace nvcuda;

#define HEADS   8
#define NSEQ    49
#define GRID7   7
#define DMODEL  512
#define BATCH   2048
#define MROWS   (BATCH * NSEQ)   // 100352 = 392 * 256
#define MTILES  (MROWS / 256)    // 392

// ---------------- scratch (no allocations allowed) ----------------
__device__ __half g_qh [(size_t)MROWS * DMODEL];    // half inputs (GEMM A)
__device__ __half g_kh [(size_t)MROWS * DMODEL];
__device__ __half g_vh [(size_t)MROWS * DMODEL];
__device__ __half g_qph[(size_t)MROWS * DMODEL];    // q projection (half)
__device__ __half g_kph[(size_t)MROWS * DMODEL];    // k projection (half)
__device__ __half g_voh[(size_t)MROWS * DMODEL];    // vo projection (half)
__device__ __half g_wqh[DMODEL * DMODEL];
__device__ __half g_wkh[DMODEL * DMODEL];
__device__ __half g_wvoh[DMODEL * DMODEL];
__device__ float  g_bvo[DMODEL];

// ---------------- small helpers ----------------
__device__ __forceinline__ uint32_t h2_bits(__half2 h) {
    union { __half2 h; uint32_t u; } cvt; cvt.h = h; return cvt.u;
}
__device__ __forceinline__ uint2 pack4(float x, float y, float z, float w) {
    return make_uint2(h2_bits(__floats2half2_rn(x, y)),
                      h2_bits(__floats2half2_rn(z, w)));
}
__device__ __forceinline__ float2 h2f(uint32_t u) {
    __half2 h = *reinterpret_cast<__half2*>(&u);
    return __half22float2(h);
}
__device__ __forceinline__ float hmulsum(uint32_t a, uint32_t b) {
    float2 fa = h2f(a), fb = h2f(b);
    return fa.x * fb.x + fa.y * fb.y;
}

// ---------------- cp.async helpers ----------------
__device__ __forceinline__ void cp16(void* smem, const void* gmem) {
    uint32_t s = (uint32_t)__cvta_generic_to_shared(smem);
    asm volatile("cp.async.cg.shared.global [%0], [%1], 16;\n" :: "r"(s), "l"(gmem));
}
__device__ __forceinline__ void cp_commit() {
    asm volatile("cp.async.commit_group;\n");
}
template <int N>
__device__ __forceinline__ void cp_wait() {
    asm volatile("cp.async.wait_group %0;\n" :: "n"(N));
}

// =====================================================================
// Input conversion: fp32 -> fp16 for queries/keys/values (one pass).
// =====================================================================
__global__ __launch_bounds__(512)
void conv_inputs(const float4* __restrict__ q, const float4* __restrict__ k,
                 const float4* __restrict__ v,
                 uint2* __restrict__ qh, uint2* __restrict__ kh,
                 uint2* __restrict__ vh)
{
    size_t i = (size_t)blockIdx.x * 512 + threadIdx.x;
    float4 a = q[i];
    float4 b = k[i];
    float4 c = v[i];
    qh[i] = pack4(a.x, a.y, a.z, a.w);
    kh[i] = pack4(b.x, b.y, b.z, b.w);
    vh[i] = pack4(c.x, c.y, c.z, c.w);
}

// =====================================================================
// Weight prep: Wvo = per-head Wo_h @ Wv_h (half), bvo; Wq/Wk -> half.
// =====================================================================
__global__ __launch_bounds__(256)
void prep_weights(const float* __restrict__ Wo, const float* __restrict__ Wv,
                  const float* __restrict__ bv,
                  const float4* __restrict__ Wq, const float4* __restrict__ Wk,
                  __half* __restrict__ wvoh, float* __restrict__ bvo,
                  uint2* __restrict__ wqh, uint2* __restrict__ wkh)
{
    int idx = blockIdx.x * 256 + threadIdx.x;   // 65536 = 512*512/4
    int n = idx >> 7, i4 = idx & 127;
    int h = n >> 6, o = n & 63;
    const float* worow = Wo + (size_t)o * DMODEL + h * 64;
    const float4* wv4  = reinterpret_cast<const float4*>(Wv);
    float4 acc = make_float4(0.f, 0.f, 0.f, 0.f);
#pragma unroll 8
    for (int t = 0; t < 64; t++) {
        float w = worow[t];
        float4 x = wv4[(size_t)(h * 64 + t) * 128 + i4];
        acc.x += w * x.x; acc.y += w * x.y; acc.z += w * x.z; acc.w += w * x.w;
    }
    reinterpret_cast<uint2*>(wvoh)[(size_t)n * 128 + i4] =
        pack4(acc.x, acc.y, acc.z, acc.w);

    float4 a = Wq[idx];
    float4 b = Wk[idx];
    wqh[idx] = pack4(a.x, a.y, a.z, a.w);
    wkh[idx] = pack4(b.x, b.y, b.z, b.w);

    if (idx < DMODEL) {
        int h2 = idx >> 6, o2 = idx & 63;
        float s = 0.f;
        for (int t = 0; t < 64; t++)
            s += Wo[(size_t)o2 * DMODEL + h2 * 64 + t] * bv[h2 * 64 + t];
        bvo[idx] = s;
    }
}

// =====================================================================
// fp16 WMMA GEMM, 3-stage cp.async pipeline, BK=64, ONE barrier/chunk.
//   C[M,512] = A[M,512] @ W[512,512]^T + bias   (all outputs fp16)
// BM=256, BN=128, 512 threads (16 warps, 4x4), 64x32 warp tiles.
// =====================================================================
#define BKH     64
#define BKP     72
#define STAGES  3
#define A_STAGE (256 * BKP * 2)                     // 36864
#define W_STAGE (128 * BKP * 2)                     // 18432
#define GEMM_SMEM (STAGES * (A_STAGE + W_STAGE))    // 165888

__global__ __launch_bounds__(512, 1)
void qkv_gemm_h(const __half* __restrict__ Aq, const __half* __restrict__ Ak,
                const __half* __restrict__ Av,
                const __half* __restrict__ Wqh, const __half* __restrict__ Wkh,
                const __half* __restrict__ Wvoh,
                const float* __restrict__ bq, const float* __restrict__ bk,
                const float* __restrict__ bvo,
                __half* __restrict__ Cq, __half* __restrict__ Ck,
                __half* __restrict__ Cv)
{
    extern __shared__ __align__(16) unsigned char dynsmem[];
    __half (*As)[256][BKP] =
        reinterpret_cast<__half (*)[256][BKP]>(dynsmem);
    __half (*Ws)[128][BKP] =
        reinterpret_cast<__half (*)[128][BKP]>(dynsmem + STAGES * A_STAGE);
    float (*stage)[16][20] = reinterpret_cast<float (*)[16][20]>(dynsmem);

    const int z = blockIdx.z;
    const __half* A    = (z == 0) ? Aq  : (z == 1) ? Ak  : Av;
    const __half* W    = (z == 0) ? Wqh : (z == 1) ? Wkh : Wvoh;
    const float*  bias = (z == 0) ? bq  : (z == 1) ? bk  : bvo;
    __half*       C    = (z == 0) ? Cq  : (z == 1) ? Ck  : Cv;

    const int tid  = threadIdx.x;
    const int warp = tid >> 5;
    const int lane = tid & 31;
    const int wm   = warp >> 2;          // 0..3 -> 64 rows each
    const int wn   = warp & 3;           // 0..3 -> 32 cols each
    const int m0   = blockIdx.y * 256;
    const int n0   = blockIdx.x * 128;

    wmma::fragment<wmma::accumulator, 16, 16, 16, float> acc[4][2];
#pragma unroll
    for (int mf = 0; mf < 4; mf++)
#pragma unroll
        for (int nf = 0; nf < 2; nf++)
            wmma::fill_fragment(acc[mf][nf], 0.0f);

    // per stage: A = 2048 cp16 (4/thread), W = 1024 cp16 (2/thread)
    auto issue_stage = [&](int kc, int s) {
#pragma unroll
        for (int r = 0; r < 4; r++) {
            int idx = tid + r * 512;
            int row = idx >> 3, lc = idx & 7;
            cp16(&As[s][row][lc * 8],
                 A + (size_t)(m0 + row) * DMODEL + kc * BKH + lc * 8);
        }
#pragma unroll
        for (int r = 0; r < 2; r++) {
            int idx = tid + r * 512;
            int row = idx >> 3, lc = idx & 7;
            cp16(&Ws[s][row][lc * 8],
                 W + (size_t)(n0 + row) * DMODEL + kc * BKH + lc * 8);
        }
        cp_commit();
    };

    const int nk = DMODEL / BKH;   // 8
    issue_stage(0, 0);
    issue_stage(1, 1);

    for (int kc = 0; kc < nk; kc++) {
        cp_wait<1>();          // group kc complete
        __syncthreads();       // all warps done with buffer (kc+2)%3
        if (kc + 2 < nk) issue_stage(kc + 2, (kc + 2) % 3);
        else             cp_commit();

        const int buf = kc % 3;
#pragma unroll
        for (int ks = 0; ks < BKH; ks += 16) {
            wmma::fragment<wmma::matrix_b, 16, 16, 16, __half, wmma::col_major> bf[2];
#pragma unroll
            for (int nf = 0; nf < 2; nf++)
                wmma::load_matrix_sync(bf[nf], &Ws[buf][wn * 32 + nf * 16][ks], BKP);
#pragma unroll
            for (int mf = 0; mf < 4; mf++) {
                wmma::fragment<wmma::matrix_a, 16, 16, 16, __half, wmma::row_major> af;
                wmma::load_matrix_sync(af, &As[buf][wm * 64 + mf * 16][ks], BKP);
#pragma unroll
                for (int nf = 0; nf < 2; nf++)
                    wmma::mma_sync(acc[mf][nf], af, bf[nf], acc[mf][nf]);
            }
        }
    }
    // stage alias covers only As[0] (chunk 6 data); all warps are past chunk 6
    // (barrier at top of kc=7), and stage[warp] is warp-private -> safe.

    // ---- epilogue: stage fragments, add bias, pack fp16, store 16B ----
#pragma unroll
    for (int mf = 0; mf < 4; mf++)
#pragma unroll
        for (int nf = 0; nf < 2; nf++) {
            wmma::store_matrix_sync(&stage[warp][0][0], acc[mf][nf], 20,
                                    wmma::mem_row_major);
            __syncwarp();
            int r  = lane >> 1;
            int c  = (lane & 1) * 8;
            int gm = m0 + wm * 64 + mf * 16 + r;
            int gn = n0 + wn * 32 + nf * 16 + c;
            float4 v0 = *reinterpret_cast<float4*>(&stage[warp][r][c]);
            float4 v1 = *reinterpret_cast<float4*>(&stage[warp][r][c + 4]);
            float4 b0 = *reinterpret_cast<const float4*>(&bias[gn]);
            float4 b1 = *reinterpret_cast<const float4*>(&bias[gn + 4]);
            uint2 p0 = pack4(v0.x + b0.x, v0.y + b0.y, v0.z + b0.z, v0.w + b0.w);
            uint2 p1 = pack4(v1.x + b1.x, v1.y + b1.y, v1.z + b1.z, v1.w + b1.w);
            *reinterpret_cast<uint4*>(&C[(size_t)gm * DMODEL + gn]) =
                make_uint4(p0.x, p0.y, p1.x, p1.y);
            __syncwarp();
        }
}

// =====================================================================
// Sparse dilated attention. One block per batch, 256 threads, 8 heads
// sequential. q/k/vo tiles all fp16; per-head output partials live in
// REGISTERS (fixed slot->thread map) across heads — no smem RMW.
//   w_ij = exp(s_ij) - 1 on Chebyshev-1 neighbors;
//   O_i  = (VOsum + sum w_ij vo_j) / (49 + sum w_ij); out = sum_h O + bo
// =====================================================================
__global__ __launch_bounds__(256)
void dilate_attn(const __half* __restrict__ qh, const __half* __restrict__ kh,
                 const __half* __restrict__ voh, const float* __restrict__ bo,
                 float* __restrict__ out)
{
    __shared__ uint4 tq[NSEQ][9];      // 64 halves/row (8 used; +1 pad)
    __shared__ uint4 tk[NSEQ][9];
    __shared__ uint4 tvo[NSEQ][9];
    __shared__ float wgt[NSEQ][8];
    __shared__ float zinv[NSEQ];
    __shared__ float vsumf[64];
    __shared__ int   nbr[NSEQ][8];
    __shared__ int   cnt[NSEQ];

    const int b   = blockIdx.x;
    const int tid = threadIdx.x;
    const size_t bbase = (size_t)b * NSEQ * DMODEL;   // element units

    if (tid < NSEQ) {
        int r = tid / GRID7, c = tid % GRID7;
        int n = 0;
#pragma unroll
        for (int dr = -1; dr <= 1; dr++)
#pragma unroll
            for (int dc = -1; dc <= 1; dc++) {
                if (dr == 0 && dc == 0) continue;
                int rr = r + dr, cc = c + dc;
                if (rr >= 0 && rr < GRID7 && cc >= 0 && cc < GRID7)
                    nbr[tid][n++] = rr * GRID7 + cc;
            }
        cnt[tid] = n;
        for (int l = n; l < 8; l++) nbr[tid][l] = 0;
    }

    // register output accumulators: slot = tid + s2*256 -> (i = slot/8, d8 = slot%8)
    float racc[2][8];
#pragma unroll
    for (int s2 = 0; s2 < 2; s2++)
#pragma unroll
        for (int e = 0; e < 8; e++) racc[s2][e] = 0.f;

    for (int h = 0; h < HEADS; h++) {
        const size_t base8 = (bbase + h * 64) / 8;    // uint4 units (8 halves)
        __syncthreads();
        // ---- load q, k, vo tiles ----
        for (int e = tid; e < NSEQ * 8; e += 256) {
            int n = e >> 3, d8 = e & 7;
            tq[n][d8]  = reinterpret_cast<const uint4*>(qh) [base8 + n * 64 + d8];
            tk[n][d8]  = reinterpret_cast<const uint4*>(kh) [base8 + n * 64 + d8];
            tvo[n][d8] = reinterpret_cast<const uint4*>(voh)[base8 + n * 64 + d8];
        }
        __syncthreads();
        // ---- sparse QK dots ----
        for (int t = tid; t < NSEQ * 8; t += 256) {
            int i = t >> 3, l = t & 7;
            float w = 0.f;
            if (l < cnt[i]) {
                int j = nbr[i][l];
                float dot = 0.f;
#pragma unroll
                for (int d8 = 0; d8 < 8; d8++) {
                    uint4 a = tq[i][d8], bb = tk[j][d8];
                    dot += hmulsum(a.x, bb.x) + hmulsum(a.y, bb.y)
                         + hmulsum(a.z, bb.z) + hmulsum(a.w, bb.w);
                }
                w = __expf(dot * 0.125f) - 1.f;
            }
            wgt[i][l] = w;
        }
        __syncthreads();
        // ---- normalizers (threads 0..48) + vo column sums (threads 64..71) ----
        if (tid < NSEQ) {
            float zz = (float)NSEQ;
#pragma unroll
            for (int l = 0; l < 8; l++) zz += wgt[tid][l];
            zinv[tid] = 1.f / zz;
        }
        if (tid >= 64 && tid < 72) {
            int d8 = tid - 64;
            float s[8];
#pragma unroll
            for (int e = 0; e < 8; e++) s[e] = 0.f;
            for (int j = 0; j < NSEQ; j++) {
                uint4 vv = tvo[j][d8];
                float2 f0 = h2f(vv.x), f1 = h2f(vv.y),
                       f2 = h2f(vv.z), f3 = h2f(vv.w);
                s[0] += f0.x; s[1] += f0.y; s[2] += f1.x; s[3] += f1.y;
                s[4] += f2.x; s[5] += f2.y; s[6] += f3.x; s[7] += f3.y;
            }
#pragma unroll
            for (int e = 0; e < 8; e++) vsumf[d8 * 8 + e] = s[e];
        }
        __syncthreads();
        // ---- output accumulate into registers ----
#pragma unroll
        for (int s2 = 0; s2 < 2; s2++) {
            int slot = tid + s2 * 256;
            if (slot < NSEQ * 8) {
                int i = slot >> 3, d8 = slot & 7;
                float a[8];
#pragma unroll
                for (int e = 0; e < 8; e++) a[e] = vsumf[d8 * 8 + e];
#pragma unroll
                for (int l = 0; l < 8; l++) {
                    float w = wgt[i][l];
                    uint4 vv = tvo[nbr[i][l]][d8];
                    float2 f0 = h2f(vv.x), f1 = h2f(vv.y),
                           f2 = h2f(vv.z), f3 = h2f(vv.w);
                    a[0] += w * f0.x; a[1] += w * f0.y;
                    a[2] += w * f1.x; a[3] += w * f1.y;
                    a[4] += w * f2.x; a[5] += w * f2.y;
                    a[6] += w * f3.x; a[7] += w * f3.y;
                }
                float zi = zinv[i];
#pragma unroll
                for (int e = 0; e < 8; e++) racc[s2][e] += a[e] * zi;
            }
        }
    }

    // ---- final: add bias, write 64-dim rows ----
#pragma unroll
    for (int s2 = 0; s2 < 2; s2++) {
        int slot = tid + s2 * 256;
        if (slot < NSEQ * 8) {
            int i = slot >> 3, d8 = slot & 7;
            float4 o0, o1;
            o0.x = racc[s2][0] + bo[d8 * 8 + 0];
            o0.y = racc[s2][1] + bo[d8 * 8 + 1];
            o0.z = racc[s2][2] + bo[d8 * 8 + 2];
            o0.w = racc[s2][3] + bo[d8 * 8 + 3];
            o1.x = racc[s2][4] + bo[d8 * 8 + 4];
            o1.y = racc[s2][5] + bo[d8 * 8 + 5];
            o1.z = racc[s2][6] + bo[d8 * 8 + 6];
            o1.w = racc[s2][7] + bo[d8 * 8 + 7];
            size_t base = (size_t)b * NSEQ * 64 + (size_t)i * 64 + d8 * 8;
            *reinterpret_cast<float4*>(&out[base])     = o0;
            *reinterpret_cast<float4*>(&out[base + 4]) = o1;
        }
    }
}

// ---------------- launch ----------------
extern "C" void kernel_launch(void* const* d_in, const int* in_sizes, int n_in,
                              void* d_out, int out_size)
{
    const float* queries = (const float*)d_in[0];
    const float* keys    = (const float*)d_in[1];
    const float* values  = (const float*)d_in[2];
    const float* Wq      = (const float*)d_in[3];
    const float* bq      = (const float*)d_in[4];
    const float* Wk      = (const float*)d_in[5];
    const float* bk      = (const float*)d_in[6];
    const float* Wv      = (const float*)d_in[7];
    const float* bv      = (const float*)d_in[8];
    const float* Wo      = (const float*)d_in[9];
    const float* bo      = (const float*)d_in[10];

    float  *bvo;
    __half *qh, *kh, *vh, *qph, *kph, *voh, *wqh, *wkh, *wvoh;
    cudaGetSymbolAddress((void**)&qh,   g_qh);
    cudaGetSymbolAddress((void**)&kh,   g_kh);
    cudaGetSymbolAddress((void**)&vh,   g_vh);
    cudaGetSymbolAddress((void**)&qph,  g_qph);
    cudaGetSymbolAddress((void**)&kph,  g_kph);
    cudaGetSymbolAddress((void**)&voh,  g_voh);
    cudaGetSymbolAddress((void**)&wqh,  g_wqh);
    cudaGetSymbolAddress((void**)&wkh,  g_wkh);
    cudaGetSymbolAddress((void**)&wvoh, g_wvoh);
    cudaGetSymbolAddress((void**)&bvo,  g_bvo);

    cudaFuncSetAttribute(qkv_gemm_h,
                         cudaFuncAttributeMaxDynamicSharedMemorySize, GEMM_SMEM);

    // 1) convert inputs fp32 -> fp16
    conv_inputs<<<(MROWS * DMODEL / 4) / 512, 512>>>(
        (const float4*)queries, (const float4*)keys, (const float4*)values,
        (uint2*)qh, (uint2*)kh, (uint2*)vh);

    // 2) fold Wo into Wv (half), convert Wq/Wk to half
    prep_weights<<<256, 256>>>(Wo, Wv, bv, (const float4*)Wq, (const float4*)Wk,
                               wvoh, bvo, (uint2*)wqh, (uint2*)wkh);

    // 3) projections: q, k, vo all fp16 out
    dim3 gridQKV(DMODEL / 128, MTILES, 3);
    qkv_gemm_h<<<gridQKV, 512, GEMM_SMEM>>>(qh, kh, vh, wqh, wkh, wvoh,
                                            bq, bk, bvo, qph, kph, voh);

    // 4) sparse dilated attention + head-summed output, straight to d_out
    dilate_attn<<<BATCH, 256>>>(qph, kph, voh, bo, (float*)d_out);
}

// round 13
// speedup vs baseline: 4.6960x; 1.0018x over previous
#include <cuda_runtime.h>
#include <cuda_fp16.h>
#include <cstdint>
#include <mma.h>
#include <math.h>

using namespace nvcuda;

#define HEADS   8
#define NSEQ    49
#define GRID7   7
#define DMODEL  512
#define BATCH   2048
#define MROWS   (BATCH * NSEQ)   // 100352 = 392 * 256
#define MTILES  (MROWS / 256)    // 392

// ---------------- scratch (no allocations allowed) ----------------
__device__ __half g_qh [(size_t)MROWS * DMODEL];    // half inputs (GEMM A)
__device__ __half g_kh [(size_t)MROWS * DMODEL];
__device__ __half g_vh [(size_t)MROWS * DMODEL];
__device__ __half g_qph[(size_t)MROWS * DMODEL];    // q projection (half)
__device__ __half g_kph[(size_t)MROWS * DMODEL];    // k projection (half)
__device__ __half g_voh[(size_t)MROWS * DMODEL];    // vo projection (half)
__device__ __half g_wqh[DMODEL * DMODEL];
__device__ __half g_wkh[DMODEL * DMODEL];
__device__ __half g_wvoh[DMODEL * DMODEL];
__device__ float  g_bvo[DMODEL];

// ---------------- small helpers ----------------
__device__ __forceinline__ uint32_t h2_bits(__half2 h) {
    union { __half2 h; uint32_t u; } cvt; cvt.h = h; return cvt.u;
}
__device__ __forceinline__ __half2 u2h2(uint32_t u) {
    union { uint32_t u; __half2 h; } cvt; cvt.u = u; return cvt.h;
}
__device__ __forceinline__ uint2 pack4(float x, float y, float z, float w) {
    return make_uint2(h2_bits(__floats2half2_rn(x, y)),
                      h2_bits(__floats2half2_rn(z, w)));
}
__device__ __forceinline__ float2 h2f(uint32_t u) {
    return __half22float2(u2h2(u));
}
// dot of 8 halves: half2 partial chain (4 products), then fp32 reduce
__device__ __forceinline__ float dot8h(uint4 a, uint4 b) {
    __half2 p = __hmul2(u2h2(a.x), u2h2(b.x));
    p = __hfma2(u2h2(a.y), u2h2(b.y), p);
    p = __hfma2(u2h2(a.z), u2h2(b.z), p);
    p = __hfma2(u2h2(a.w), u2h2(b.w), p);
    float2 f = __half22float2(p);
    return f.x + f.y;
}

// ---------------- cp.async helpers ----------------
__device__ __forceinline__ void cp16(void* smem, const void* gmem) {
    uint32_t s = (uint32_t)__cvta_generic_to_shared(smem);
    asm volatile("cp.async.cg.shared.global [%0], [%1], 16;\n" :: "r"(s), "l"(gmem));
}
__device__ __forceinline__ void cp_commit() {
    asm volatile("cp.async.commit_group;\n");
}
template <int N>
__device__ __forceinline__ void cp_wait() {
    asm volatile("cp.async.wait_group %0;\n" :: "n"(N));
}

// =====================================================================
// Input conversion: fp32 -> fp16 for queries/keys/values (one pass).
// =====================================================================
__global__ __launch_bounds__(512)
void conv_inputs(const float4* __restrict__ q, const float4* __restrict__ k,
                 const float4* __restrict__ v,
                 uint2* __restrict__ qh, uint2* __restrict__ kh,
                 uint2* __restrict__ vh)
{
    size_t i = (size_t)blockIdx.x * 512 + threadIdx.x;
    float4 a = q[i];
    float4 b = k[i];
    float4 c = v[i];
    qh[i] = pack4(a.x, a.y, a.z, a.w);
    kh[i] = pack4(b.x, b.y, b.z, b.w);
    vh[i] = pack4(c.x, c.y, c.z, c.w);
}

// =====================================================================
// Weight prep: Wvo = per-head Wo_h @ Wv_h (half), bvo; Wq/Wk -> half.
// =====================================================================
__global__ __launch_bounds__(256)
void prep_weights(const float* __restrict__ Wo, const float* __restrict__ Wv,
                  const float* __restrict__ bv,
                  const float4* __restrict__ Wq, const float4* __restrict__ Wk,
                  __half* __restrict__ wvoh, float* __restrict__ bvo,
                  uint2* __restrict__ wqh, uint2* __restrict__ wkh)
{
    int idx = blockIdx.x * 256 + threadIdx.x;   // 65536 = 512*512/4
    int n = idx >> 7, i4 = idx & 127;
    int h = n >> 6, o = n & 63;
    const float* worow = Wo + (size_t)o * DMODEL + h * 64;
    const float4* wv4  = reinterpret_cast<const float4*>(Wv);
    float4 acc = make_float4(0.f, 0.f, 0.f, 0.f);
#pragma unroll 8
    for (int t = 0; t < 64; t++) {
        float w = worow[t];
        float4 x = wv4[(size_t)(h * 64 + t) * 128 + i4];
        acc.x += w * x.x; acc.y += w * x.y; acc.z += w * x.z; acc.w += w * x.w;
    }
    reinterpret_cast<uint2*>(wvoh)[(size_t)n * 128 + i4] =
        pack4(acc.x, acc.y, acc.z, acc.w);

    float4 a = Wq[idx];
    float4 b = Wk[idx];
    wqh[idx] = pack4(a.x, a.y, a.z, a.w);
    wkh[idx] = pack4(b.x, b.y, b.z, b.w);

    if (idx < DMODEL) {
        int h2 = idx >> 6, o2 = idx & 63;
        float s = 0.f;
        for (int t = 0; t < 64; t++)
            s += Wo[(size_t)o2 * DMODEL + h2 * 64 + t] * bv[h2 * 64 + t];
        bvo[idx] = s;
    }
}

// =====================================================================
// fp16 WMMA GEMM, 3-stage cp.async pipeline, BK=64, one barrier/chunk,
// 64x64 warp tiles. Pipeline order (PROVEN): wait -> sync -> issue ->
// compute. The sync after the wait publishes every thread's group-kc
// copies AND certifies buffer (kc+2)%3 (last read at compute kc-1) free.
//   C[M,512] = A[M,512] @ W[512,512]^T + bias   (all outputs fp16)
// BM=256, BN=128, 256 threads (8 warps, 4m x 2n).
// =====================================================================
#define BKH     64
#define BKP     72
#define STAGES  3
#define A_STAGE (256 * BKP * 2)                     // 36864
#define W_STAGE (128 * BKP * 2)                     // 18432
#define GEMM_SMEM (STAGES * (A_STAGE + W_STAGE))    // 165888

__global__ __launch_bounds__(256, 1)
void qkv_gemm_h(const __half* __restrict__ Aq, const __half* __restrict__ Ak,
                const __half* __restrict__ Av,
                const __half* __restrict__ Wqh, const __half* __restrict__ Wkh,
                const __half* __restrict__ Wvoh,
                const float* __restrict__ bq, const float* __restrict__ bk,
                const float* __restrict__ bvo,
                __half* __restrict__ Cq, __half* __restrict__ Ck,
                __half* __restrict__ Cv)
{
    extern __shared__ __align__(16) unsigned char dynsmem[];
    __half (*As)[256][BKP] =
        reinterpret_cast<__half (*)[256][BKP]>(dynsmem);
    __half (*Ws)[128][BKP] =
        reinterpret_cast<__half (*)[128][BKP]>(dynsmem + STAGES * A_STAGE);
    float (*stage)[16][20] = reinterpret_cast<float (*)[16][20]>(dynsmem);

    const int z = blockIdx.z;
    const __half* A    = (z == 0) ? Aq  : (z == 1) ? Ak  : Av;
    const __half* W    = (z == 0) ? Wqh : (z == 1) ? Wkh : Wvoh;
    const float*  bias = (z == 0) ? bq  : (z == 1) ? bk  : bvo;
    __half*       C    = (z == 0) ? Cq  : (z == 1) ? Ck  : Cv;

    const int tid  = threadIdx.x;
    const int warp = tid >> 5;
    const int lane = tid & 31;
    const int wm   = warp >> 1;          // 0..3 -> 64 rows each
    const int wn   = warp & 1;           // 0..1 -> 64 cols each
    const int m0   = blockIdx.y * 256;
    const int n0   = blockIdx.x * 128;

    wmma::fragment<wmma::accumulator, 16, 16, 16, float> acc[4][4];
#pragma unroll
    for (int mf = 0; mf < 4; mf++)
#pragma unroll
        for (int nf = 0; nf < 4; nf++)
            wmma::fill_fragment(acc[mf][nf], 0.0f);

    // per stage: A = 2048 cp16 (8/thread), W = 1024 cp16 (4/thread)
    auto issue_stage = [&](int kc, int s) {
#pragma unroll
        for (int r = 0; r < 8; r++) {
            int idx = tid + r * 256;
            int row = idx >> 3, lc = idx & 7;
            cp16(&As[s][row][lc * 8],
                 A + (size_t)(m0 + row) * DMODEL + kc * BKH + lc * 8);
        }
#pragma unroll
        for (int r = 0; r < 4; r++) {
            int idx = tid + r * 256;
            int row = idx >> 3, lc = idx & 7;
            cp16(&Ws[s][row][lc * 8],
                 W + (size_t)(n0 + row) * DMODEL + kc * BKH + lc * 8);
        }
        cp_commit();
    };

    const int nk = DMODEL / BKH;   // 8
    issue_stage(0, 0);
    issue_stage(1, 1);

    for (int kc = 0; kc < nk; kc++) {
        cp_wait<1>();          // this thread's group kc complete
        __syncthreads();       // ALL threads' group kc visible; buf (kc+2)%3 free
        if (kc + 2 < nk) issue_stage(kc + 2, (kc + 2) % 3);
        else             cp_commit();   // keep group count uniform

        const int buf = kc % 3;
#pragma unroll
        for (int ks = 0; ks < BKH; ks += 16) {
            wmma::fragment<wmma::matrix_b, 16, 16, 16, __half, wmma::col_major> bf[4];
#pragma unroll
            for (int nf = 0; nf < 4; nf++)
                wmma::load_matrix_sync(bf[nf], &Ws[buf][wn * 64 + nf * 16][ks], BKP);
#pragma unroll
            for (int mf = 0; mf < 4; mf++) {
                wmma::fragment<wmma::matrix_a, 16, 16, 16, __half, wmma::row_major> af;
                wmma::load_matrix_sync(af, &As[buf][wm * 64 + mf * 16][ks], BKP);
#pragma unroll
                for (int nf = 0; nf < 4; nf++)
                    wmma::mma_sync(acc[mf][nf], af, bf[nf], acc[mf][nf]);
            }
        }
    }
    __syncthreads();   // all warps done with final tiles before stage alias reuse

    // ---- epilogue: stage fragments, add bias, pack fp16, store 16B ----
#pragma unroll
    for (int mf = 0; mf < 4; mf++)
#pragma unroll
        for (int nf = 0; nf < 4; nf++) {
            wmma::store_matrix_sync(&stage[warp][0][0], acc[mf][nf], 20,
                                    wmma::mem_row_major);
            __syncwarp();
            int r  = lane >> 1;
            int c  = (lane & 1) * 8;
            int gm = m0 + wm * 64 + mf * 16 + r;
            int gn = n0 + wn * 64 + nf * 16 + c;
            float4 v0 = *reinterpret_cast<float4*>(&stage[warp][r][c]);
            float4 v1 = *reinterpret_cast<float4*>(&stage[warp][r][c + 4]);
            float4 b0 = *reinterpret_cast<const float4*>(&bias[gn]);
            float4 b1 = *reinterpret_cast<const float4*>(&bias[gn + 4]);
            uint2 p0 = pack4(v0.x + b0.x, v0.y + b0.y, v0.z + b0.z, v0.w + b0.w);
            uint2 p1 = pack4(v1.x + b1.x, v1.y + b1.y, v1.z + b1.z, v1.w + b1.w);
            *reinterpret_cast<uint4*>(&C[(size_t)gm * DMODEL + gn]) =
                make_uint4(p0.x, p0.y, p1.x, p1.y);
            __syncwarp();
        }
}

// =====================================================================
// Sparse dilated attention. One block per batch, 256 threads, 8 heads
// sequential; 3 barriers/head. HFMA2 partial dots; zinv folded into the
// QK phase via 8-lane shuffles with FULL-WARP participation (predicated
// slots, full mask — no __activemask); vo column sums on threads
// 192..199; output partials accumulate in registers across heads.
// =====================================================================
__global__ __launch_bounds__(256)
void dilate_attn(const __half* __restrict__ qh, const __half* __restrict__ kh,
                 const __half* __restrict__ voh, const float* __restrict__ bo,
                 float* __restrict__ out)
{
    __shared__ uint4 tq[NSEQ][9];      // 64 halves/row (8 used; +1 pad)
    __shared__ uint4 tk[NSEQ][9];
    __shared__ uint4 tvo[NSEQ][9];
    __shared__ float wgt[NSEQ][8];
    __shared__ float zinv[NSEQ];
    __shared__ float vsumf[64];
    __shared__ int   nbr[NSEQ][8];
    __shared__ int   cnt[NSEQ];

    const int b   = blockIdx.x;
    const int tid = threadIdx.x;
    const size_t bbase = (size_t)b * NSEQ * DMODEL;   // element units

    if (tid < NSEQ) {
        int r = tid / GRID7, c = tid % GRID7;
        int n = 0;
#pragma unroll
        for (int dr = -1; dr <= 1; dr++)
#pragma unroll
            for (int dc = -1; dc <= 1; dc++) {
                if (dr == 0 && dc == 0) continue;
                int rr = r + dr, cc = c + dc;
                if (rr >= 0 && rr < GRID7 && cc >= 0 && cc < GRID7)
                    nbr[tid][n++] = rr * GRID7 + cc;
            }
        cnt[tid] = n;
        for (int l = n; l < 8; l++) nbr[tid][l] = 0;
    }

    // register output accumulators: slot = tid + s2*256 -> (i = slot/8, d8 = slot%8)
    float racc[2][8];
#pragma unroll
    for (int s2 = 0; s2 < 2; s2++)
#pragma unroll
        for (int e = 0; e < 8; e++) racc[s2][e] = 0.f;

    for (int h = 0; h < HEADS; h++) {
        const size_t base8 = (bbase + h * 64) / 8;    // uint4 units (8 halves)
        __syncthreads();    // previous output phase done with tiles (and nbr init)
        // ---- load q, k, vo tiles ----
        for (int e = tid; e < NSEQ * 8; e += 256) {
            int n = e >> 3, d8 = e & 7;
            tq[n][d8]  = reinterpret_cast<const uint4*>(qh) [base8 + n * 64 + d8];
            tk[n][d8]  = reinterpret_cast<const uint4*>(kh) [base8 + n * 64 + d8];
            tvo[n][d8] = reinterpret_cast<const uint4*>(voh)[base8 + n * 64 + d8];
        }
        __syncthreads();
        // ---- sparse QK dots + per-row zinv (uniform full-warp shuffles) ----
#pragma unroll
        for (int s2 = 0; s2 < 2; s2++) {
            int slot = tid + s2 * 256;
            bool valid = slot < NSEQ * 8;
            int i = valid ? (slot >> 3) : 0;
            int l = slot & 7;
            float w = 0.f;
            if (valid && l < cnt[i]) {
                int j = nbr[i][l];
                float dot = 0.f;
#pragma unroll
                for (int d8 = 0; d8 < 8; d8++)
                    dot += dot8h(tq[i][d8], tk[j][d8]);
                w = __expf(dot * 0.125f) - 1.f;
            }
            if (valid) wgt[i][l] = w;
            float zs = w;   // all 32 lanes participate; invalid lanes carry 0
            zs += __shfl_down_sync(0xFFFFFFFFu, zs, 4, 8);
            zs += __shfl_down_sync(0xFFFFFFFFu, zs, 2, 8);
            zs += __shfl_down_sync(0xFFFFFFFFu, zs, 1, 8);
            if (valid && l == 0) zinv[i] = __fdividef(1.f, (float)NSEQ + zs);
        }
        // ---- vo column sums (threads 192..199: single-slot threads) ----
        if (tid >= 192 && tid < 200) {
            int d8 = tid - 192;
            float s[8];
#pragma unroll
            for (int e = 0; e < 8; e++) s[e] = 0.f;
            for (int j = 0; j < NSEQ; j++) {
                uint4 vv = tvo[j][d8];
                float2 f0 = h2f(vv.x), f1 = h2f(vv.y),
                       f2 = h2f(vv.z), f3 = h2f(vv.w);
                s[0] += f0.x; s[1] += f0.y; s[2] += f1.x; s[3] += f1.y;
                s[4] += f2.x; s[5] += f2.y; s[6] += f3.x; s[7] += f3.y;
            }
#pragma unroll
            for (int e = 0; e < 8; e++) vsumf[d8 * 8 + e] = s[e];
        }
        __syncthreads();
        // ---- output accumulate into registers ----
#pragma unroll
        for (int s2 = 0; s2 < 2; s2++) {
            int slot = tid + s2 * 256;
            if (slot < NSEQ * 8) {
                int i = slot >> 3, d8 = slot & 7;
                float a[8];
#pragma unroll
                for (int e = 0; e < 8; e++) a[e] = vsumf[d8 * 8 + e];
#pragma unroll
                for (int l = 0; l < 8; l++) {
                    float w = wgt[i][l];
                    uint4 vv = tvo[nbr[i][l]][d8];
                    float2 f0 = h2f(vv.x), f1 = h2f(vv.y),
                           f2 = h2f(vv.z), f3 = h2f(vv.w);
                    a[0] += w * f0.x; a[1] += w * f0.y;
                    a[2] += w * f1.x; a[3] += w * f1.y;
                    a[4] += w * f2.x; a[5] += w * f2.y;
                    a[6] += w * f3.x; a[7] += w * f3.y;
                }
                float zi = zinv[i];
#pragma unroll
                for (int e = 0; e < 8; e++) racc[s2][e] += a[e] * zi;
            }
        }
    }

    // ---- final: add bias, write 64-dim rows ----
#pragma unroll
    for (int s2 = 0; s2 < 2; s2++) {
        int slot = tid + s2 * 256;
        if (slot < NSEQ * 8) {
            int i = slot >> 3, d8 = slot & 7;
            float4 o0, o1;
            o0.x = racc[s2][0] + bo[d8 * 8 + 0];
            o0.y = racc[s2][1] + bo[d8 * 8 + 1];
            o0.z = racc[s2][2] + bo[d8 * 8 + 2];
            o0.w = racc[s2][3] + bo[d8 * 8 + 3];
            o1.x = racc[s2][4] + bo[d8 * 8 + 4];
            o1.y = racc[s2][5] + bo[d8 * 8 + 5];
            o1.z = racc[s2][6] + bo[d8 * 8 + 6];
            o1.w = racc[s2][7] + bo[d8 * 8 + 7];
            size_t base = (size_t)b * NSEQ * 64 + (size_t)i * 64 + d8 * 8;
            *reinterpret_cast<float4*>(&out[base])     = o0;
            *reinterpret_cast<float4*>(&out[base + 4]) = o1;
        }
    }
}

// ---------------- launch ----------------
extern "C" void kernel_launch(void* const* d_in, const int* in_sizes, int n_in,
                              void* d_out, int out_size)
{
    const float* queries = (const float*)d_in[0];
    const float* keys    = (const float*)d_in[1];
    const float* values  = (const float*)d_in[2];
    const float* Wq      = (const float*)d_in[3];
    const float* bq      = (const float*)d_in[4];
    const float* Wk      = (const float*)d_in[5];
    const float* bk      = (const float*)d_in[6];
    const float* Wv      = (const float*)d_in[7];
    const float* bv      = (const float*)d_in[8];
    const float* Wo      = (const float*)d_in[9];
    const float* bo      = (const float*)d_in[10];

    float  *bvo;
    __half *qh, *kh, *vh, *qph, *kph, *voh, *wqh, *wkh, *wvoh;
    cudaGetSymbolAddress((void**)&qh,   g_qh);
    cudaGetSymbolAddress((void**)&kh,   g_kh);
    cudaGetSymbolAddress((void**)&vh,   g_vh);
    cudaGetSymbolAddress((void**)&qph,  g_qph);
    cudaGetSymbolAddress((void**)&kph,  g_kph);
    cudaGetSymbolAddress((void**)&voh,  g_voh);
    cudaGetSymbolAddress((void**)&wqh,  g_wqh);
    cudaGetSymbolAddress((void**)&wkh,  g_wkh);
    cudaGetSymbolAddress((void**)&wvoh, g_wvoh);
    cudaGetSymbolAddress((void**)&bvo,  g_bvo);

    cudaFuncSetAttribute(qkv_gemm_h,
                         cudaFuncAttributeMaxDynamicSharedMemorySize, GEMM_SMEM);

    // 1) convert inputs fp32 -> fp16
    conv_inputs<<<(MROWS * DMODEL / 4) / 512, 512>>>(
        (const float4*)queries, (const float4*)keys, (const float4*)values,
        (uint2*)qh, (uint2*)kh, (uint2*)vh);

    // 2) fold Wo into Wv (half), convert Wq/Wk to half
    prep_weights<<<256, 256>>>(Wo, Wv, bv, (const float4*)Wq, (const float4*)Wk,
                               wvoh, bvo, (uint2*)wqh, (uint2*)wkh);

    // 3) projections: q, k, vo all fp16 out
    dim3 gridQKV(DMODEL / 128, MTILES, 3);
    qkv_gemm_h<<<gridQKV, 256, GEMM_SMEM>>>(qh, kh, vh, wqh, wkh, wvoh,
                                            bq, bk, bvo, qph, kph, voh);

    // 4) sparse dilated attention + head-summed output, straight to d_out
    dilate_attn<<<BATCH, 256>>>(qph, kph, voh, bo, (float*)d_out);
}

// round 14
// speedup vs baseline: 4.9083x; 1.0452x over previous
#include <cuda_runtime.h>
#include <cuda_fp16.h>
#include <cstdint>
#include <mma.h>
#include <math.h>

using namespace nvcuda;

#define HEADS   8
#define NSEQ    49
#define GRID7   7
#define DMODEL  512
#define BATCH   2048
#define MROWS   (BATCH * NSEQ)   // 100352 = 784 * 128
#define MTILES  (MROWS / 128)    // 784

// ---------------- scratch (no allocations allowed) ----------------
__device__ __half g_qh [(size_t)MROWS * DMODEL];    // half inputs (GEMM A)
__device__ __half g_kh [(size_t)MROWS * DMODEL];
__device__ __half g_vh [(size_t)MROWS * DMODEL];
__device__ __half g_qph[(size_t)MROWS * DMODEL];    // q projection (half)
__device__ __half g_kph[(size_t)MROWS * DMODEL];    // k projection (half)
__device__ __half g_voh[(size_t)MROWS * DMODEL];    // vo projection (half)
__device__ __half g_wqh[DMODEL * DMODEL];
__device__ __half g_wkh[DMODEL * DMODEL];
__device__ __half g_wvoh[DMODEL * DMODEL];
__device__ float  g_bvo[DMODEL];

// ---------------- small helpers ----------------
__device__ __forceinline__ uint32_t h2_bits(__half2 h) {
    union { __half2 h; uint32_t u; } cvt; cvt.h = h; return cvt.u;
}
__device__ __forceinline__ __half2 u2h2(uint32_t u) {
    union { uint32_t u; __half2 h; } cvt; cvt.u = u; return cvt.h;
}
__device__ __forceinline__ uint2 pack4(float x, float y, float z, float w) {
    return make_uint2(h2_bits(__floats2half2_rn(x, y)),
                      h2_bits(__floats2half2_rn(z, w)));
}
__device__ __forceinline__ float2 h2f(uint32_t u) {
    return __half22float2(u2h2(u));
}
// dot of 8 halves: half2 partial chain (4 products), then fp32 reduce
__device__ __forceinline__ float dot8h(uint4 a, uint4 b) {
    __half2 p = __hmul2(u2h2(a.x), u2h2(b.x));
    p = __hfma2(u2h2(a.y), u2h2(b.y), p);
    p = __hfma2(u2h2(a.z), u2h2(b.z), p);
    p = __hfma2(u2h2(a.w), u2h2(b.w), p);
    float2 f = __half22float2(p);
    return f.x + f.y;
}

// ---------------- cp.async helpers ----------------
__device__ __forceinline__ void cp16(void* smem, const void* gmem) {
    uint32_t s = (uint32_t)__cvta_generic_to_shared(smem);
    asm volatile("cp.async.cg.shared.global [%0], [%1], 16;\n" :: "r"(s), "l"(gmem));
}
__device__ __forceinline__ void cp_commit() {
    asm volatile("cp.async.commit_group;\n");
}
template <int N>
__device__ __forceinline__ void cp_wait() {
    asm volatile("cp.async.wait_group %0;\n" :: "n"(N));
}

// =====================================================================
// Input conversion: fp32 -> fp16 for queries/keys/values (one pass).
// =====================================================================
__global__ __launch_bounds__(512)
void conv_inputs(const float4* __restrict__ q, const float4* __restrict__ k,
                 const float4* __restrict__ v,
                 uint2* __restrict__ qh, uint2* __restrict__ kh,
                 uint2* __restrict__ vh)
{
    size_t i = (size_t)blockIdx.x * 512 + threadIdx.x;
    float4 a = q[i];
    float4 b = k[i];
    float4 c = v[i];
    qh[i] = pack4(a.x, a.y, a.z, a.w);
    kh[i] = pack4(b.x, b.y, b.z, b.w);
    vh[i] = pack4(c.x, c.y, c.z, c.w);
}

// =====================================================================
// Weight prep: Wvo = per-head Wo_h @ Wv_h (half), bvo; Wq/Wk -> half.
// =====================================================================
__global__ __launch_bounds__(256)
void prep_weights(const float* __restrict__ Wo, const float* __restrict__ Wv,
                  const float* __restrict__ bv,
                  const float4* __restrict__ Wq, const float4* __restrict__ Wk,
                  __half* __restrict__ wvoh, float* __restrict__ bvo,
                  uint2* __restrict__ wqh, uint2* __restrict__ wkh)
{
    int idx = blockIdx.x * 256 + threadIdx.x;   // 65536 = 512*512/4
    int n = idx >> 7, i4 = idx & 127;
    int h = n >> 6, o = n & 63;
    const float* worow = Wo + (size_t)o * DMODEL + h * 64;
    const float4* wv4  = reinterpret_cast<const float4*>(Wv);
    float4 acc = make_float4(0.f, 0.f, 0.f, 0.f);
#pragma unroll 8
    for (int t = 0; t < 64; t++) {
        float w = worow[t];
        float4 x = wv4[(size_t)(h * 64 + t) * 128 + i4];
        acc.x += w * x.x; acc.y += w * x.y; acc.z += w * x.z; acc.w += w * x.w;
    }
    reinterpret_cast<uint2*>(wvoh)[(size_t)n * 128 + i4] =
        pack4(acc.x, acc.y, acc.z, acc.w);

    float4 a = Wq[idx];
    float4 b = Wk[idx];
    wqh[idx] = pack4(a.x, a.y, a.z, a.w);
    wkh[idx] = pack4(b.x, b.y, b.z, b.w);

    if (idx < DMODEL) {
        int h2 = idx >> 6, o2 = idx & 63;
        float s = 0.f;
        for (int t = 0; t < 64; t++)
            s += Wo[(size_t)o2 * DMODEL + h2 * 64 + t] * bv[h2 * 64 + t];
        bvo[idx] = s;
    }
}

// =====================================================================
// fp16 WMMA GEMM, 3-stage cp.async pipeline, BK=64, one barrier/chunk,
// 64x32 warp tiles (proven ratio). BM=BN=128, 256 threads (8 warps,
// 2m x 4n), smem 110.6KB -> TWO CTAs PER SM: 16 warps/SM in two
// independent pipelines whose barriers/bubbles interleave.
// Pipeline order (PROVEN): wait -> sync -> issue -> compute.
//   C[M,512] = A[M,512] @ W[512,512]^T + bias   (all outputs fp16)
// =====================================================================
#define BKH     64
#define BKP     72
#define STAGES  3
#define A_STAGE (128 * BKP * 2)                     // 18432
#define W_STAGE (128 * BKP * 2)                     // 18432
#define GEMM_SMEM (STAGES * (A_STAGE + W_STAGE))    // 110592

__global__ __launch_bounds__(256, 2)
void qkv_gemm_h(const __half* __restrict__ Aq, const __half* __restrict__ Ak,
                const __half* __restrict__ Av,
                const __half* __restrict__ Wqh, const __half* __restrict__ Wkh,
                const __half* __restrict__ Wvoh,
                const float* __restrict__ bq, const float* __restrict__ bk,
                const float* __restrict__ bvo,
                __half* __restrict__ Cq, __half* __restrict__ Ck,
                __half* __restrict__ Cv)
{
    extern __shared__ __align__(16) unsigned char dynsmem[];
    __half (*As)[128][BKP] =
        reinterpret_cast<__half (*)[128][BKP]>(dynsmem);
    __half (*Ws)[128][BKP] =
        reinterpret_cast<__half (*)[128][BKP]>(dynsmem + STAGES * A_STAGE);
    float (*stage)[16][20] = reinterpret_cast<float (*)[16][20]>(dynsmem);

    const int z = blockIdx.z;
    const __half* A    = (z == 0) ? Aq  : (z == 1) ? Ak  : Av;
    const __half* W    = (z == 0) ? Wqh : (z == 1) ? Wkh : Wvoh;
    const float*  bias = (z == 0) ? bq  : (z == 1) ? bk  : bvo;
    __half*       C    = (z == 0) ? Cq  : (z == 1) ? Ck  : Cv;

    const int tid  = threadIdx.x;
    const int warp = tid >> 5;
    const int lane = tid & 31;
    const int wm   = warp >> 2;          // 0..1 -> 64 rows each
    const int wn   = warp & 3;           // 0..3 -> 32 cols each
    const int m0   = blockIdx.y * 128;
    const int n0   = blockIdx.x * 128;

    wmma::fragment<wmma::accumulator, 16, 16, 16, float> acc[4][2];
#pragma unroll
    for (int mf = 0; mf < 4; mf++)
#pragma unroll
        for (int nf = 0; nf < 2; nf++)
            wmma::fill_fragment(acc[mf][nf], 0.0f);

    // per stage: A = 1024 cp16 (4/thread), W = 1024 cp16 (4/thread)
    auto issue_stage = [&](int kc, int s) {
#pragma unroll
        for (int r = 0; r < 4; r++) {
            int idx = tid + r * 256;
            int row = idx >> 3, lc = idx & 7;
            cp16(&As[s][row][lc * 8],
                 A + (size_t)(m0 + row) * DMODEL + kc * BKH + lc * 8);
        }
#pragma unroll
        for (int r = 0; r < 4; r++) {
            int idx = tid + r * 256;
            int row = idx >> 3, lc = idx & 7;
            cp16(&Ws[s][row][lc * 8],
                 W + (size_t)(n0 + row) * DMODEL + kc * BKH + lc * 8);
        }
        cp_commit();
    };

    const int nk = DMODEL / BKH;   // 8
    issue_stage(0, 0);
    issue_stage(1, 1);

    for (int kc = 0; kc < nk; kc++) {
        cp_wait<1>();          // this thread's group kc complete
        __syncthreads();       // ALL threads' group kc visible; buf (kc+2)%3 free
        if (kc + 2 < nk) issue_stage(kc + 2, (kc + 2) % 3);
        else             cp_commit();   // keep group count uniform

        const int buf = kc % 3;
#pragma unroll
        for (int ks = 0; ks < BKH; ks += 16) {
            wmma::fragment<wmma::matrix_b, 16, 16, 16, __half, wmma::col_major> bf[2];
#pragma unroll
            for (int nf = 0; nf < 2; nf++)
                wmma::load_matrix_sync(bf[nf], &Ws[buf][wn * 32 + nf * 16][ks], BKP);
#pragma unroll
            for (int mf = 0; mf < 4; mf++) {
                wmma::fragment<wmma::matrix_a, 16, 16, 16, __half, wmma::row_major> af;
                wmma::load_matrix_sync(af, &As[buf][wm * 64 + mf * 16][ks], BKP);
#pragma unroll
                for (int nf = 0; nf < 2; nf++)
                    wmma::mma_sync(acc[mf][nf], af, bf[nf], acc[mf][nf]);
            }
        }
    }
    __syncthreads();   // all warps done with final tiles before stage alias reuse

    // ---- epilogue: stage fragments, add bias, pack fp16, store 16B ----
#pragma unroll
    for (int mf = 0; mf < 4; mf++)
#pragma unroll
        for (int nf = 0; nf < 2; nf++) {
            wmma::store_matrix_sync(&stage[warp][0][0], acc[mf][nf], 20,
                                    wmma::mem_row_major);
            __syncwarp();
            int r  = lane >> 1;
            int c  = (lane & 1) * 8;
            int gm = m0 + wm * 64 + mf * 16 + r;
            int gn = n0 + wn * 32 + nf * 16 + c;
            float4 v0 = *reinterpret_cast<float4*>(&stage[warp][r][c]);
            float4 v1 = *reinterpret_cast<float4*>(&stage[warp][r][c + 4]);
            float4 b0 = *reinterpret_cast<const float4*>(&bias[gn]);
            float4 b1 = *reinterpret_cast<const float4*>(&bias[gn + 4]);
            uint2 p0 = pack4(v0.x + b0.x, v0.y + b0.y, v0.z + b0.z, v0.w + b0.w);
            uint2 p1 = pack4(v1.x + b1.x, v1.y + b1.y, v1.z + b1.z, v1.w + b1.w);
            *reinterpret_cast<uint4*>(&C[(size_t)gm * DMODEL + gn]) =
                make_uint4(p0.x, p0.y, p1.x, p1.y);
            __syncwarp();
        }
}

// =====================================================================
// Sparse dilated attention. One block per batch, 256 threads, 8 heads
// sequential; 3 barriers/head. HFMA2 partial dots; zinv folded into the
// QK phase via 8-lane shuffles (full-warp uniform participation);
// vo column sums on threads 192..199; output partials in registers.
// =====================================================================
__global__ __launch_bounds__(256)
void dilate_attn(const __half* __restrict__ qh, const __half* __restrict__ kh,
                 const __half* __restrict__ voh, const float* __restrict__ bo,
                 float* __restrict__ out)
{
    __shared__ uint4 tq[NSEQ][9];      // 64 halves/row (8 used; +1 pad)
    __shared__ uint4 tk[NSEQ][9];
    __shared__ uint4 tvo[NSEQ][9];
    __shared__ float wgt[NSEQ][8];
    __shared__ float zinv[NSEQ];
    __shared__ float vsumf[64];
    __shared__ int   nbr[NSEQ][8];
    __shared__ int   cnt[NSEQ];

    const int b   = blockIdx.x;
    const int tid = threadIdx.x;
    const size_t bbase = (size_t)b * NSEQ * DMODEL;   // element units

    if (tid < NSEQ) {
        int r = tid / GRID7, c = tid % GRID7;
        int n = 0;
#pragma unroll
        for (int dr = -1; dr <= 1; dr++)
#pragma unroll
            for (int dc = -1; dc <= 1; dc++) {
                if (dr == 0 && dc == 0) continue;
                int rr = r + dr, cc = c + dc;
                if (rr >= 0 && rr < GRID7 && cc >= 0 && cc < GRID7)
                    nbr[tid][n++] = rr * GRID7 + cc;
            }
        cnt[tid] = n;
        for (int l = n; l < 8; l++) nbr[tid][l] = 0;
    }

    // register output accumulators: slot = tid + s2*256 -> (i = slot/8, d8 = slot%8)
    float racc[2][8];
#pragma unroll
    for (int s2 = 0; s2 < 2; s2++)
#pragma unroll
        for (int e = 0; e < 8; e++) racc[s2][e] = 0.f;

    for (int h = 0; h < HEADS; h++) {
        const size_t base8 = (bbase + h * 64) / 8;    // uint4 units (8 halves)
        __syncthreads();    // previous output phase done with tiles (and nbr init)
        // ---- load q, k, vo tiles ----
        for (int e = tid; e < NSEQ * 8; e += 256) {
            int n = e >> 3, d8 = e & 7;
            tq[n][d8]  = reinterpret_cast<const uint4*>(qh) [base8 + n * 64 + d8];
            tk[n][d8]  = reinterpret_cast<const uint4*>(kh) [base8 + n * 64 + d8];
            tvo[n][d8] = reinterpret_cast<const uint4*>(voh)[base8 + n * 64 + d8];
        }
        __syncthreads();
        // ---- sparse QK dots + per-row zinv (uniform full-warp shuffles) ----
#pragma unroll
        for (int s2 = 0; s2 < 2; s2++) {
            int slot = tid + s2 * 256;
            bool valid = slot < NSEQ * 8;
            int i = valid ? (slot >> 3) : 0;
            int l = slot & 7;
            float w = 0.f;
            if (valid && l < cnt[i]) {
                int j = nbr[i][l];
                float dot = 0.f;
#pragma unroll
                for (int d8 = 0; d8 < 8; d8++)
                    dot += dot8h(tq[i][d8], tk[j][d8]);
                w = __expf(dot * 0.125f) - 1.f;
            }
            if (valid) wgt[i][l] = w;
            float zs = w;   // all 32 lanes participate; invalid lanes carry 0
            zs += __shfl_down_sync(0xFFFFFFFFu, zs, 4, 8);
            zs += __shfl_down_sync(0xFFFFFFFFu, zs, 2, 8);
            zs += __shfl_down_sync(0xFFFFFFFFu, zs, 1, 8);
            if (valid && l == 0) zinv[i] = __fdividef(1.f, (float)NSEQ + zs);
        }
        // ---- vo column sums (threads 192..199: single-slot threads) ----
        if (tid >= 192 && tid < 200) {
            int d8 = tid - 192;
            float s[8];
#pragma unroll
            for (int e = 0; e < 8; e++) s[e] = 0.f;
            for (int j = 0; j < NSEQ; j++) {
                uint4 vv = tvo[j][d8];
                float2 f0 = h2f(vv.x), f1 = h2f(vv.y),
                       f2 = h2f(vv.z), f3 = h2f(vv.w);
                s[0] += f0.x; s[1] += f0.y; s[2] += f1.x; s[3] += f1.y;
                s[4] += f2.x; s[5] += f2.y; s[6] += f3.x; s[7] += f3.y;
            }
#pragma unroll
            for (int e = 0; e < 8; e++) vsumf[d8 * 8 + e] = s[e];
        }
        __syncthreads();
        // ---- output accumulate into registers ----
#pragma unroll
        for (int s2 = 0; s2 < 2; s2++) {
            int slot = tid + s2 * 256;
            if (slot < NSEQ * 8) {
                int i = slot >> 3, d8 = slot & 7;
                float a[8];
#pragma unroll
                for (int e = 0; e < 8; e++) a[e] = vsumf[d8 * 8 + e];
#pragma unroll
                for (int l = 0; l < 8; l++) {
                    float w = wgt[i][l];
                    uint4 vv = tvo[nbr[i][l]][d8];
                    float2 f0 = h2f(vv.x), f1 = h2f(vv.y),
                           f2 = h2f(vv.z), f3 = h2f(vv.w);
                    a[0] += w * f0.x; a[1] += w * f0.y;
                    a[2] += w * f1.x; a[3] += w * f1.y;
                    a[4] += w * f2.x; a[5] += w * f2.y;
                    a[6] += w * f3.x; a[7] += w * f3.y;
                }
                float zi = zinv[i];
#pragma unroll
                for (int e = 0; e < 8; e++) racc[s2][e] += a[e] * zi;
            }
        }
    }

    // ---- final: add bias, write 64-dim rows ----
#pragma unroll
    for (int s2 = 0; s2 < 2; s2++) {
        int slot = tid + s2 * 256;
        if (slot < NSEQ * 8) {
            int i = slot >> 3, d8 = slot & 7;
            float4 o0, o1;
            o0.x = racc[s2][0] + bo[d8 * 8 + 0];
            o0.y = racc[s2][1] + bo[d8 * 8 + 1];
            o0.z = racc[s2][2] + bo[d8 * 8 + 2];
            o0.w = racc[s2][3] + bo[d8 * 8 + 3];
            o1.x = racc[s2][4] + bo[d8 * 8 + 4];
            o1.y = racc[s2][5] + bo[d8 * 8 + 5];
            o1.z = racc[s2][6] + bo[d8 * 8 + 6];
            o1.w = racc[s2][7] + bo[d8 * 8 + 7];
            size_t base = (size_t)b * NSEQ * 64 + (size_t)i * 64 + d8 * 8;
            *reinterpret_cast<float4*>(&out[base])     = o0;
            *reinterpret_cast<float4*>(&out[base + 4]) = o1;
        }
    }
}

// ---------------- launch ----------------
extern "C" void kernel_launch(void* const* d_in, const int* in_sizes, int n_in,
                              void* d_out, int out_size)
{
    const float* queries = (const float*)d_in[0];
    const float* keys    = (const float*)d_in[1];
    const float* values  = (const float*)d_in[2];
    const float* Wq      = (const float*)d_in[3];
    const float* bq      = (const float*)d_in[4];
    const float* Wk      = (const float*)d_in[5];
    const float* bk      = (const float*)d_in[6];
    const float* Wv      = (const float*)d_in[7];
    const float* bv      = (const float*)d_in[8];
    const float* Wo      = (const float*)d_in[9];
    const float* bo      = (const float*)d_in[10];

    float  *bvo;
    __half *qh, *kh, *vh, *qph, *kph, *voh, *wqh, *wkh, *wvoh;
    cudaGetSymbolAddress((void**)&qh,   g_qh);
    cudaGetSymbolAddress((void**)&kh,   g_kh);
    cudaGetSymbolAddress((void**)&vh,   g_vh);
    cudaGetSymbolAddress((void**)&qph,  g_qph);
    cudaGetSymbolAddress((void**)&kph,  g_kph);
    cudaGetSymbolAddress((void**)&voh,  g_voh);
    cudaGetSymbolAddress((void**)&wqh,  g_wqh);
    cudaGetSymbolAddress((void**)&wkh,  g_wkh);
    cudaGetSymbolAddress((void**)&wvoh, g_wvoh);
    cudaGetSymbolAddress((void**)&bvo,  g_bvo);

    cudaFuncSetAttribute(qkv_gemm_h,
                         cudaFuncAttributeMaxDynamicSharedMemorySize, GEMM_SMEM);

    // 1) convert inputs fp32 -> fp16
    conv_inputs<<<(MROWS * DMODEL / 4) / 512, 512>>>(
        (const float4*)queries, (const float4*)keys, (const float4*)values,
        (uint2*)qh, (uint2*)kh, (uint2*)vh);

    // 2) fold Wo into Wv (half), convert Wq/Wk to half
    prep_weights<<<256, 256>>>(Wo, Wv, bv, (const float4*)Wq, (const float4*)Wk,
                               wvoh, bvo, (uint2*)wqh, (uint2*)wkh);

    // 3) projections: q, k, vo all fp16 out (2 CTAs/SM GEMM)
    dim3 gridQKV(DMODEL / 128, MTILES, 3);
    qkv_gemm_h<<<gridQKV, 256, GEMM_SMEM>>>(qh, kh, vh, wqh, wkh, wvoh,
                                            bq, bk, bvo, qph, kph, voh);

    // 4) sparse dilated attention + head-summed output, straight to d_out
    dilate_attn<<<BATCH, 256>>>(qph, kph, voh, bo, (float*)d_out);
}